// round 1
// baseline (speedup 1.0000x reference)
#include <cuda_runtime.h>
#include <cuda_bf16.h>
#include <cstdint>

// ---------------------------------------------------------------------------
// HyperMoMixLinear: B=4, S=128 (T=512 tokens), IN=OUT=1024, C=256, K=4,
// NI=NO=32, D1=D2=32768.
//
// Pipeline (coeffs folded into activations so each stage is ONE big GEMM):
//   c      = silu(x @ Wc + bc)                        [512,256]
//   coeffs = softmax(silu(c@Wm1+bm1) @ Wm2 + bm2)     [512,4]
//   ratio  = c @ Wr + br                              [512]
//   biasor = c @ Wb + bb                              [512,1024]
//   g1[t, k*256+j] = coeffs[t,k]*silu(c@W1a[k]+b1a[k])[512,1024]
//   M1     = g1 @ W1b_flat + coeffs @ b1b             [512,32768] (scratch)
//   x1o[t,g,o] = sum_i x[t,g*32+i]*M1[t,g*1024+i*32+o]  (stored transposed)
//   (same with W2a/W2b -> M2, reuse scratch)
//   out[t,g*32+o] = x2o * ratio[t] + biasor
// ---------------------------------------------------------------------------

#define T_TOK 512
#define C_DIM 256
#define IN_DIM 1024
#define OUT_DIM 1024
#define K_EXP 4
#define D_BIG 32768
#define KC 1024   // K_EXP * C_DIM

// -------------------- device scratch (no runtime allocation) ---------------
__device__ float g_c[T_TOK * C_DIM];
__device__ float g_g[T_TOK * KC];
__device__ float g_coeffs[T_TOK * K_EXP];
__device__ float g_ratio[T_TOK];
__device__ float g_biasor[T_TOK * OUT_DIM];
__device__ float g_x1o[T_TOK * OUT_DIM];
__device__ float g_M[T_TOK * D_BIG];     // 64 MB, reused for M1 then M2

__device__ __forceinline__ float silu_f(float v) {
    return v / (1.0f + __expf(-v));
}

// -------------------- small GEMM: 64x64x16 tiles, 4x4 per thread -----------
// EPI 0: out = acc + bias[n]
// EPI 1: out = silu(acc + bias[n])
// EPI 2: out = coeffs[m*4 + blockIdx.z] * silu(acc + bias[n])   (expert gen)
template<int EPI>
__global__ void sgemm64(const float* __restrict__ A, const float* __restrict__ B,
                        float* __restrict__ Cmat,
                        int Kd, int lda, int ldb, int ldc,
                        const float* __restrict__ bias,
                        const float* __restrict__ coeffs,
                        int b_zstride, int bias_zstride, int col_zstride)
{
    const int BM = 64, BN = 64, BK = 16;
    __shared__ float As[BK][BM];
    __shared__ float Bs[BK][BN];
    int tid = threadIdx.x;
    int kz = blockIdx.z;
    B += (long)kz * b_zstride;
    bias += kz * bias_zstride;
    int m0 = blockIdx.y * BM;
    int n0 = blockIdx.x * BN;
    int tx = tid % 16, ty = tid / 16;
    int arow = tid / 4, aq = tid % 4;      // A: 64 rows x 4 float4
    int brow = tid / 16, bq = tid % 16;    // B: 16 k-rows x 16 float4
    float acc[4][4] = {};

    for (int k0 = 0; k0 < Kd; k0 += BK) {
        float4 av = *(const float4*)&A[(m0 + arow) * lda + k0 + aq * 4];
        As[aq * 4 + 0][arow] = av.x;
        As[aq * 4 + 1][arow] = av.y;
        As[aq * 4 + 2][arow] = av.z;
        As[aq * 4 + 3][arow] = av.w;
        *(float4*)&Bs[brow][bq * 4] =
            *(const float4*)&B[(k0 + brow) * ldb + n0 + bq * 4];
        __syncthreads();
#pragma unroll
        for (int k = 0; k < BK; k++) {
            float a[4], b[4];
#pragma unroll
            for (int i = 0; i < 4; i++) a[i] = As[k][ty * 4 + i];
#pragma unroll
            for (int j = 0; j < 4; j++) b[j] = Bs[k][tx * 4 + j];
#pragma unroll
            for (int i = 0; i < 4; i++)
#pragma unroll
                for (int j = 0; j < 4; j++) acc[i][j] += a[i] * b[j];
        }
        __syncthreads();
    }

#pragma unroll
    for (int i = 0; i < 4; i++) {
        int m = m0 + ty * 4 + i;
        float cf = 1.0f;
        if (EPI == 2) cf = coeffs[m * K_EXP + kz];
#pragma unroll
        for (int j = 0; j < 4; j++) {
            int n = n0 + tx * 4 + j;                 // slice-local column
            float v = acc[i][j] + bias[n];
            if (EPI == 1) v = silu_f(v);
            if (EPI == 2) v = cf * silu_f(v);
            Cmat[m * ldc + kz * col_zstride + n] = v;
        }
    }
}

// -------------------- big GEMM: M=512, N=32768, K=1024 ---------------------
// 128x128x8 tiles, 8x8 per thread, 256 threads. grid = (M/128, N/128) with
// m on blockIdx.x so consecutive blocks share the B tile (L2 reuse of the
// 128 MB weight matrix).
__global__ void sgemm_big(const float* __restrict__ A, const float* __restrict__ B,
                          float* __restrict__ Cmat,
                          const float* __restrict__ bB,     // [K_EXP, D_BIG]
                          const float* __restrict__ coeffs) // [T, K_EXP]
{
    __shared__ float As[8][128];
    __shared__ float Bs[8][128];
    int tid = threadIdx.x;
    int m0 = blockIdx.x * 128;
    int n0 = blockIdx.y * 128;
    int tx = tid % 16, ty = tid / 16;
    int arow = tid / 2, aq = tid % 2;      // A: 128 rows x 2 float4
    int brow = tid / 32, bq = tid % 32;    // B: 8 k-rows x 32 float4
    float acc[8][8] = {};

    const float* Aptr = A + (m0 + arow) * KC + aq * 4;
    const float* Bptr = B + (long)brow * D_BIG + n0 + bq * 4;

    for (int k0 = 0; k0 < KC; k0 += 8) {
        float4 av = *(const float4*)(Aptr + k0);
        float4 bv = *(const float4*)(Bptr + (long)k0 * D_BIG);
        As[aq * 4 + 0][arow] = av.x;
        As[aq * 4 + 1][arow] = av.y;
        As[aq * 4 + 2][arow] = av.z;
        As[aq * 4 + 3][arow] = av.w;
        *(float4*)&Bs[brow][bq * 4] = bv;
        __syncthreads();
#pragma unroll
        for (int k = 0; k < 8; k++) {
            float4 a0 = *(const float4*)&As[k][ty * 8];
            float4 a1 = *(const float4*)&As[k][ty * 8 + 4];
            float4 b0 = *(const float4*)&Bs[k][tx * 8];
            float4 b1 = *(const float4*)&Bs[k][tx * 8 + 4];
            float a[8] = {a0.x, a0.y, a0.z, a0.w, a1.x, a1.y, a1.z, a1.w};
            float b[8] = {b0.x, b0.y, b0.z, b0.w, b1.x, b1.y, b1.z, b1.w};
#pragma unroll
            for (int i = 0; i < 8; i++)
#pragma unroll
                for (int j = 0; j < 8; j++) acc[i][j] += a[i] * b[j];
        }
        __syncthreads();
    }

#pragma unroll
    for (int i = 0; i < 8; i++) {
        int m = m0 + ty * 8 + i;
        float c0 = coeffs[m * 4 + 0], c1 = coeffs[m * 4 + 1];
        float c2 = coeffs[m * 4 + 2], c3 = coeffs[m * 4 + 3];
#pragma unroll
        for (int j = 0; j < 8; j++) {
            int n = n0 + tx * 8 + j;
            float bias = c0 * bB[n] + c1 * bB[D_BIG + n] +
                         c2 * bB[2 * D_BIG + n] + c3 * bB[3 * D_BIG + n];
            Cmat[(long)m * D_BIG + n] = acc[i][j] + bias;
        }
    }
}

// -------------------- mixer: coeffs + ratio per token ----------------------
__global__ void mixer_kernel(const float* __restrict__ c,
                             const float* __restrict__ Wm1, const float* __restrict__ bm1,
                             const float* __restrict__ Wm2, const float* __restrict__ bm2,
                             const float* __restrict__ Wr,  const float* __restrict__ br,
                             float* __restrict__ coeffs, float* __restrict__ ratio)
{
    __shared__ float cs[C_DIM];
    __shared__ float ms[C_DIM];
    __shared__ float red[C_DIM];
    __shared__ float lg[K_EXP];
    int t = blockIdx.x, tid = threadIdx.x;

    cs[tid] = c[t * C_DIM + tid];
    __syncthreads();

    float acc = bm1[tid];
#pragma unroll 8
    for (int i = 0; i < C_DIM; i++) acc += cs[i] * Wm1[i * C_DIM + tid];
    ms[tid] = silu_f(acc);
    red[tid] = cs[tid] * Wr[tid];
    __syncthreads();

    if (tid < K_EXP) {
        float l = bm2[tid];
#pragma unroll 8
        for (int i = 0; i < C_DIM; i++) l += ms[i] * Wm2[i * K_EXP + tid];
        lg[tid] = l;
    }
    for (int s = 128; s > 0; s >>= 1) {
        __syncthreads();
        if (tid < s) red[tid] += red[tid + s];
    }
    __syncthreads();

    if (tid == 0) {
        ratio[t] = red[0] + br[0];
        float mx = fmaxf(fmaxf(lg[0], lg[1]), fmaxf(lg[2], lg[3]));
        float e0 = __expf(lg[0] - mx), e1 = __expf(lg[1] - mx);
        float e2 = __expf(lg[2] - mx), e3 = __expf(lg[3] - mx);
        float inv = 1.0f / (e0 + e1 + e2 + e3);
        coeffs[t * 4 + 0] = e0 * inv;
        coeffs[t * 4 + 1] = e1 * inv;
        coeffs[t * 4 + 2] = e2 * inv;
        coeffs[t * 4 + 3] = e3 * inv;
    }
}

// -------------------- Monarch stage: per-(token,g) 32x32 GEMV --------------
// STAGE 1: out[t, o*32+g] = sum_i x[t,g*32+i] * M[t, g*1024+i*32+o]
//          (transposed store == x2 layout for stage 2)
// STAGE 2: out[t, g*32+o] = (sum_i ...) * ratio[t] + biasor[t, g*32+o]
template<int STAGE>
__global__ void monarch_kernel(const float* __restrict__ X,
                               const float* __restrict__ Mbuf,
                               float* __restrict__ out,
                               const float* __restrict__ ratio,
                               const float* __restrict__ biasor)
{
    __shared__ float xs[1024];
    int t = blockIdx.x;
    int tid = threadIdx.x;   // 256
#pragma unroll
    for (int i = tid; i < 1024; i += 256) xs[i] = X[t * 1024 + i];
    __syncthreads();

    int o = tid & 31, w = tid >> 5;
    const float* Mrow = Mbuf + (long)t * D_BIG;
#pragma unroll
    for (int gi = 0; gi < 4; gi++) {
        int g = w * 4 + gi;
        float acc = 0.0f;
        const float* mp = Mrow + g * 1024 + o;
#pragma unroll
        for (int i = 0; i < 32; i++) acc += xs[g * 32 + i] * mp[i * 32];
        if (STAGE == 1) {
            out[t * 1024 + o * 32 + g] = acc;           // transposed
        } else {
            int idx = t * 1024 + g * 32 + o;
            out[idx] = acc * ratio[t] + biasor[idx];
        }
    }
}

// ---------------------------------------------------------------------------
extern "C" void kernel_launch(void* const* d_in, const int* in_sizes, int n_in,
                              void* d_out, int out_size)
{
    const float* x   = (const float*)d_in[0];
    const float* Wc  = (const float*)d_in[1];
    const float* bc  = (const float*)d_in[2];
    const float* W1a = (const float*)d_in[3];
    const float* b1a = (const float*)d_in[4];
    const float* W1b = (const float*)d_in[5];
    const float* b1b = (const float*)d_in[6];
    const float* W2a = (const float*)d_in[7];
    const float* b2a = (const float*)d_in[8];
    const float* W2b = (const float*)d_in[9];
    const float* b2b = (const float*)d_in[10];
    const float* Wm1 = (const float*)d_in[11];
    const float* bm1 = (const float*)d_in[12];
    const float* Wm2 = (const float*)d_in[13];
    const float* bm2 = (const float*)d_in[14];
    const float* Wb  = (const float*)d_in[15];
    const float* bb  = (const float*)d_in[16];
    const float* Wr  = (const float*)d_in[17];
    const float* br  = (const float*)d_in[18];
    float* out = (float*)d_out;

    float *p_c, *p_g, *p_co, *p_ra, *p_bi, *p_x1, *p_M;
    cudaGetSymbolAddress((void**)&p_c,  g_c);
    cudaGetSymbolAddress((void**)&p_g,  g_g);
    cudaGetSymbolAddress((void**)&p_co, g_coeffs);
    cudaGetSymbolAddress((void**)&p_ra, g_ratio);
    cudaGetSymbolAddress((void**)&p_bi, g_biasor);
    cudaGetSymbolAddress((void**)&p_x1, g_x1o);
    cudaGetSymbolAddress((void**)&p_M,  g_M);

    // 1. c = silu(x @ Wc + bc)
    sgemm64<1><<<dim3(C_DIM / 64, T_TOK / 64, 1), 256>>>(
        x, Wc, p_c, IN_DIM, IN_DIM, C_DIM, C_DIM, bc, nullptr, 0, 0, 0);

    // 2. coeffs (softmax), ratio
    mixer_kernel<<<T_TOK, C_DIM>>>(p_c, Wm1, bm1, Wm2, bm2, Wr, br, p_co, p_ra);

    // 3. biasor = c @ Wb + bb
    sgemm64<0><<<dim3(OUT_DIM / 64, T_TOK / 64, 1), 256>>>(
        p_c, Wb, p_bi, C_DIM, C_DIM, OUT_DIM, OUT_DIM, bb, nullptr, 0, 0, 0);

    // 4. g1 = coeffs * silu(c @ W1a + b1a)   (per expert, z = expert)
    sgemm64<2><<<dim3(C_DIM / 64, T_TOK / 64, K_EXP), 256>>>(
        p_c, W1a, p_g, C_DIM, C_DIM, C_DIM, KC, b1a, p_co,
        C_DIM * C_DIM, C_DIM, C_DIM);

    // 5. M1 = g1 @ W1b_flat + coeffs @ b1b
    sgemm_big<<<dim3(T_TOK / 128, D_BIG / 128), 256>>>(p_g, W1b, p_M, b1b, p_co);

    // 6. Monarch stage 1 (writes x2-transposed)
    monarch_kernel<1><<<T_TOK, 256>>>(x, p_M, p_x1, nullptr, nullptr);

    // 7. g2 = coeffs * silu(c @ W2a + b2a)
    sgemm64<2><<<dim3(C_DIM / 64, T_TOK / 64, K_EXP), 256>>>(
        p_c, W2a, p_g, C_DIM, C_DIM, C_DIM, KC, b2a, p_co,
        C_DIM * C_DIM, C_DIM, C_DIM);

    // 8. M2 = g2 @ W2b_flat + coeffs @ b2b   (reuse scratch)
    sgemm_big<<<dim3(T_TOK / 128, D_BIG / 128), 256>>>(p_g, W2b, p_M, b2b, p_co);

    // 9. Monarch stage 2 + final epilogue
    monarch_kernel<2><<<T_TOK, 256>>>(p_x1, p_M, out, p_ra, p_bi);
}

// round 5
// speedup vs baseline: 1.5961x; 1.5961x over previous
#include <cuda_runtime.h>
#include <cuda_bf16.h>
#include <cstdint>
#include <cstddef>

// ---------------------------------------------------------------------------
// HyperMoMixLinear on GB300 (sm_103a harness, PLAIN sm_103 ptx target).
// tcgen05 is unavailable (harness compiles via compute_103 -> 'a' features
// rejected). Big hypernet GEMMs (512x32768x1024, x2) use mma.sync bf16
// (HMMA, sm_80+ plain feature) with 3-term bf16 split for fp32-like accuracy.
// ---------------------------------------------------------------------------

#define T_TOK 512
#define C_DIM 256
#define IN_DIM 1024
#define OUT_DIM 1024
#define K_EXP 4
#define D_BIG 32768
#define KC 1024   // K_EXP * C_DIM  == GEMM K

// -------------------- device scratch (no runtime allocation) ---------------
__device__ float g_c[T_TOK * C_DIM];
__device__ __nv_bfloat16 g_Ahi[T_TOK * KC];
__device__ __nv_bfloat16 g_Alo[T_TOK * KC];
__device__ float g_coeffs[T_TOK * K_EXP];
__device__ float g_ratio[T_TOK];
__device__ float g_biasor[T_TOK * OUT_DIM];
__device__ float g_x1o[T_TOK * OUT_DIM];
__device__ float g_M[(size_t)T_TOK * D_BIG];     // 64 MB scratch (M1 then M2)

__device__ __forceinline__ float silu_f(float v) {
    return v / (1.0f + __expf(-v));
}

__device__ __forceinline__ uint32_t smem_u32(const void* p) {
    uint32_t a;
    asm("{ .reg .u64 t; cvta.to.shared.u64 t, %1; cvt.u32.u64 %0, t; }"
        : "=r"(a) : "l"(p));
    return a;
}

#define CP_ASYNC16(dst, src) \
    asm volatile("cp.async.cg.shared.global [%0], [%1], 16;" \
                 :: "r"(dst), "l"(src) : "memory")
#define CP_COMMIT() asm volatile("cp.async.commit_group;" ::: "memory")
#define CP_WAIT0()  asm volatile("cp.async.wait_group 0;" ::: "memory")

#define LDSM4(r, addr) \
    asm volatile("ldmatrix.sync.aligned.m8n8.x4.shared.b16 {%0,%1,%2,%3}, [%4];" \
        : "=r"((r)[0]), "=r"((r)[1]), "=r"((r)[2]), "=r"((r)[3]) : "r"(addr))
#define LDSM4T(r, addr) \
    asm volatile("ldmatrix.sync.aligned.m8n8.x4.trans.shared.b16 {%0,%1,%2,%3}, [%4];" \
        : "=r"((r)[0]), "=r"((r)[1]), "=r"((r)[2]), "=r"((r)[3]) : "r"(addr))

#define MMA_BF16(d, a, b0v, b1v) \
    asm volatile("mma.sync.aligned.m16n8k16.row.col.f32.bf16.bf16.f32 " \
        "{%0,%1,%2,%3}, {%4,%5,%6,%7}, {%8,%9}, {%0,%1,%2,%3};" \
        : "+f"((d)[0]), "+f"((d)[1]), "+f"((d)[2]), "+f"((d)[3]) \
        : "r"((a)[0]), "r"((a)[1]), "r"((a)[2]), "r"((a)[3]), \
          "r"(b0v), "r"(b1v))

__device__ __forceinline__ uint32_t pack_bf16x2(float a, float b) {
    __nv_bfloat162 h = __floats2bfloat162_rn(a, b);
    return *(uint32_t*)&h;
}

// -------------------- small GEMM: 64x64x16 tiles, 4x4 per thread -----------
// EPI 0: out = acc + bias[n]          (fp32)
// EPI 1: out = silu(acc + bias[n])    (fp32)
// EPI 2: coeffs[m,kz]*silu(acc+bias)  -> bf16 hi/lo split outputs
template<int EPI>
__global__ void sgemm64(const float* __restrict__ A, const float* __restrict__ B,
                        float* __restrict__ Cmat,
                        int Kd, int lda, int ldb, int ldc,
                        const float* __restrict__ bias,
                        const float* __restrict__ coeffs,
                        int b_zstride, int bias_zstride, int col_zstride,
                        __nv_bfloat16* __restrict__ ghi,
                        __nv_bfloat16* __restrict__ glo)
{
    const int BM = 64, BN = 64, BK = 16;
    __shared__ float As[BK][BM];
    __shared__ float Bs[BK][BN];
    int tid = threadIdx.x;
    int kz = blockIdx.z;
    B += (long)kz * b_zstride;
    bias += kz * bias_zstride;
    int m0 = blockIdx.y * BM;
    int n0 = blockIdx.x * BN;
    int tx = tid % 16, ty = tid / 16;
    int arow = tid / 4, aq = tid % 4;
    int brow = tid / 16, bq = tid % 16;
    float acc[4][4] = {};

    for (int k0 = 0; k0 < Kd; k0 += BK) {
        float4 av = *(const float4*)&A[(m0 + arow) * lda + k0 + aq * 4];
        As[aq * 4 + 0][arow] = av.x;
        As[aq * 4 + 1][arow] = av.y;
        As[aq * 4 + 2][arow] = av.z;
        As[aq * 4 + 3][arow] = av.w;
        *(float4*)&Bs[brow][bq * 4] =
            *(const float4*)&B[(k0 + brow) * ldb + n0 + bq * 4];
        __syncthreads();
#pragma unroll
        for (int k = 0; k < BK; k++) {
            float a[4], b[4];
#pragma unroll
            for (int i = 0; i < 4; i++) a[i] = As[k][ty * 4 + i];
#pragma unroll
            for (int j = 0; j < 4; j++) b[j] = Bs[k][tx * 4 + j];
#pragma unroll
            for (int i = 0; i < 4; i++)
#pragma unroll
                for (int j = 0; j < 4; j++) acc[i][j] += a[i] * b[j];
        }
        __syncthreads();
    }

#pragma unroll
    for (int i = 0; i < 4; i++) {
        int m = m0 + ty * 4 + i;
        float cf = 1.0f;
        if (EPI == 2) cf = coeffs[m * K_EXP + kz];
#pragma unroll
        for (int j = 0; j < 4; j++) {
            int n = n0 + tx * 4 + j;
            float v = acc[i][j] + bias[n];
            if (EPI == 1) v = silu_f(v);
            if (EPI == 2) {
                v = cf * silu_f(v);
                int idx = m * ldc + kz * col_zstride + n;
                __nv_bfloat16 h = __float2bfloat16(v);
                ghi[idx] = h;
                glo[idx] = __float2bfloat16(v - __bfloat162float(h));
            } else {
                Cmat[m * ldc + kz * col_zstride + n] = v;
            }
        }
    }
}

// -------------------- big GEMM on mma.sync (HMMA bf16, 3-term split) -------
// C[512,32768] = A[512,1024] @ W[1024,32768] + coeffs@bB
// A pre-split bf16 hi/lo in gmem; W fp32, converted to hi/lo in-kernel.
// CTA tile 128x128, BK=32, double-buffered smem, 8 warps of 64x32.
//
// smem per stage (32 KB):
//   A: 128 rows x 128 B  (hi bytes [0,64), lo [64,128), swizzled)   16 KB
//   B: hi plane 32 x 256 B, lo plane 32 x 256 B (swizzled)          16 KB
__global__ void __launch_bounds__(256, 1) bgemm_mma(
    const __nv_bfloat16* __restrict__ Ahi, const __nv_bfloat16* __restrict__ Alo,
    const float* __restrict__ W,
    float* __restrict__ C,
    const float* __restrict__ bB,      // [K_EXP, D_BIG]
    const float* __restrict__ coeffs)  // [T, K_EXP]
{
    extern __shared__ __align__(128) char smem[];
    const uint32_t sbase = smem_u32(smem);
    const int tid = threadIdx.x, wid = tid >> 5, lane = tid & 31;
    const int m0 = blockIdx.x * 128, n0 = blockIdx.y * 128;
    const int warp_m = wid & 1, warp_n = wid >> 1;   // 2 x 4 warps

    const uint32_t STG = 32768;   // bytes per stage
    const uint32_t BOFF = 16384;  // B planes offset within stage

    float acc[4][4][4] = {};

    // ---- A cp.async per-thread geometry (4 x 16B per iter) ----
    // G = tid + i*256: sel = G>>9, m = (G>>2)&127, gq = G&3
    const int a_m_lo = tid >> 2;           // + (i&1)*64
    const int a_gq = tid & 3;
    const uint32_t a_xor = ((uint32_t)(a_m_lo & 7)) << 4;
    // smem col offset for (sel, gq): (sel*64 + gq*16) ^ a_xor
    // ---- B per-thread geometry (4 x float4 per iter) ----
    const int b_krow = tid >> 5;           // + i*8
    const int b_c4 = tid & 31;
    const uint32_t b_sto = ((uint32_t)(b_c4 * 8)) ^ (((uint32_t)b_krow) << 4);

    float bf[16];                           // prefetched W values

    // ---- warp ldmatrix geometry ----
    const int aRow = warp_m * 64 + (lane & 15);
    const uint32_t axor = ((uint32_t)(aRow & 7)) << 4;
    const uint32_t aKhalf = ((lane >> 4) & 1) * 16;
    uint32_t kOffA[2][2];                  // [sel][ks16]
#pragma unroll
    for (int sel = 0; sel < 2; sel++)
#pragma unroll
        for (int ks = 0; ks < 2; ks++)
            kOffA[sel][ks] = ((uint32_t)(sel * 64 + ks * 32) + aKhalf) ^ axor;
    const uint32_t aBase = (uint32_t)aRow * 128;

    const int kLoc = (lane & 7) | (((lane >> 3) & 1) << 3);
    const uint32_t bxor = ((uint32_t)(kLoc & 7)) << 4;
    const uint32_t bBase = (uint32_t)kLoc * 256;
    uint32_t nbp[2];
#pragma unroll
    for (int p = 0; p < 2; p++)
        nbp[p] = ((uint32_t)((warp_n * 32 + p * 16 + ((lane >> 4) & 1) * 8) * 2)) ^ bxor;

    auto issueA = [&](int it, int buf) {
        uint32_t sA = sbase + buf * STG;
        int k0 = it * 32;
#pragma unroll
        for (int i = 0; i < 4; i++) {
            int sel = i >> 1;
            int m = a_m_lo + (i & 1) * 64;
            const __nv_bfloat16* src =
                (sel ? Alo : Ahi) + (size_t)(m0 + m) * KC + k0 + a_gq * 8;
            uint32_t dst = sA + (uint32_t)m * 128 +
                           (((uint32_t)(sel * 64 + a_gq * 16)) ^ a_xor);
            CP_ASYNC16(dst, src);
        }
        CP_COMMIT();
    };
    auto loadB = [&](int it) {
        int k0 = it * 32;
#pragma unroll
        for (int i = 0; i < 4; i++) {
            float4 v = *(const float4*)(W + (size_t)(k0 + b_krow + i * 8) * D_BIG
                                          + n0 + b_c4 * 4);
            bf[i * 4 + 0] = v.x; bf[i * 4 + 1] = v.y;
            bf[i * 4 + 2] = v.z; bf[i * 4 + 3] = v.w;
        }
    };
    auto storeB = [&](int buf) {
        uint32_t sB = sbase + buf * STG + BOFF;
#pragma unroll
        for (int i = 0; i < 4; i++) {
            float v0 = bf[i * 4], v1 = bf[i * 4 + 1], v2 = bf[i * 4 + 2], v3 = bf[i * 4 + 3];
            __nv_bfloat16 h0 = __float2bfloat16(v0), h1 = __float2bfloat16(v1);
            __nv_bfloat16 h2 = __float2bfloat16(v2), h3 = __float2bfloat16(v3);
            uint2 hv, lv;
            hv.x = pack_bf16x2(__bfloat162float(h0), __bfloat162float(h1));
            hv.y = pack_bf16x2(__bfloat162float(h2), __bfloat162float(h3));
            lv.x = pack_bf16x2(v0 - __bfloat162float(h0), v1 - __bfloat162float(h1));
            lv.y = pack_bf16x2(v2 - __bfloat162float(h2), v3 - __bfloat162float(h3));
            uint32_t off = (uint32_t)(b_krow + i * 8) * 256 + b_sto;
            *(uint2*)(smem + (buf * STG + BOFF) + off) = hv;
            *(uint2*)(smem + (buf * STG + BOFF) + 8192 + off) = lv;
        }
        (void)sB;
    };

    // ---- preamble: stage 0 ----
    issueA(0, 0);
    loadB(0);
    storeB(0);
    CP_WAIT0();
    __syncthreads();

    // ---- main loop ----
    for (int it = 0; it < 32; ++it) {
        int cur = it & 1;
        if (it < 31) { issueA(it + 1, cur ^ 1); loadB(it + 1); }

        uint32_t sA = sbase + cur * STG;
        uint32_t sB = sA + BOFF;
#pragma unroll
        for (int ks = 0; ks < 2; ks++) {
            uint32_t ah[4][4], al[4][4], bb[2][4];
#pragma unroll
            for (int mt = 0; mt < 4; mt++)
                LDSM4(ah[mt], sA + aBase + mt * 2048 + kOffA[0][ks]);
#pragma unroll
            for (int p = 0; p < 2; p++)
                LDSM4T(bb[p], sB + ks * 4096 + bBase + nbp[p]);
            // hi * hi
#pragma unroll
            for (int mt = 0; mt < 4; mt++)
#pragma unroll
                for (int nt = 0; nt < 4; nt++)
                    MMA_BF16(acc[mt][nt], ah[mt],
                             bb[nt >> 1][(nt & 1) * 2], bb[nt >> 1][(nt & 1) * 2 + 1]);
            // lo * hi
#pragma unroll
            for (int mt = 0; mt < 4; mt++)
                LDSM4(al[mt], sA + aBase + mt * 2048 + kOffA[1][ks]);
#pragma unroll
            for (int mt = 0; mt < 4; mt++)
#pragma unroll
                for (int nt = 0; nt < 4; nt++)
                    MMA_BF16(acc[mt][nt], al[mt],
                             bb[nt >> 1][(nt & 1) * 2], bb[nt >> 1][(nt & 1) * 2 + 1]);
            // hi * lo
#pragma unroll
            for (int p = 0; p < 2; p++)
                LDSM4T(bb[p], sB + 8192 + ks * 4096 + bBase + nbp[p]);
#pragma unroll
            for (int mt = 0; mt < 4; mt++)
#pragma unroll
                for (int nt = 0; nt < 4; nt++)
                    MMA_BF16(acc[mt][nt], ah[mt],
                             bb[nt >> 1][(nt & 1) * 2], bb[nt >> 1][(nt & 1) * 2 + 1]);
        }

        if (it < 31) { CP_WAIT0(); storeB(cur ^ 1); }
        __syncthreads();
    }

    // ---- epilogue: direct stores with mixed-expert bias ----
    const int mw = m0 + warp_m * 64;
    const int nw = n0 + warp_n * 32;
    const int row = lane >> 2, col = (lane & 3) * 2;
#pragma unroll
    for (int nt = 0; nt < 4; nt++) {
        int n = nw + nt * 8 + col;
        float bv[4][2];
#pragma unroll
        for (int e = 0; e < 4; e++) {
            bv[e][0] = bB[(size_t)e * D_BIG + n];
            bv[e][1] = bB[(size_t)e * D_BIG + n + 1];
        }
#pragma unroll
        for (int mt = 0; mt < 4; mt++) {
            int m = mw + mt * 16 + row;
            float4 c0 = *(const float4*)(coeffs + m * 4);
            float4 c1 = *(const float4*)(coeffs + (m + 8) * 4);
            float bias00 = c0.x * bv[0][0] + c0.y * bv[1][0] + c0.z * bv[2][0] + c0.w * bv[3][0];
            float bias01 = c0.x * bv[0][1] + c0.y * bv[1][1] + c0.z * bv[2][1] + c0.w * bv[3][1];
            float bias10 = c1.x * bv[0][0] + c1.y * bv[1][0] + c1.z * bv[2][0] + c1.w * bv[3][0];
            float bias11 = c1.x * bv[0][1] + c1.y * bv[1][1] + c1.z * bv[2][1] + c1.w * bv[3][1];
            float2 o0 = { acc[mt][nt][0] + bias00, acc[mt][nt][1] + bias01 };
            float2 o1 = { acc[mt][nt][2] + bias10, acc[mt][nt][3] + bias11 };
            *(float2*)(C + (size_t)m * D_BIG + n) = o0;
            *(float2*)(C + (size_t)(m + 8) * D_BIG + n) = o1;
        }
    }
}
#define BGEMM_SMEM (2 * 32768)

// -------------------- mixer: coeffs + ratio per token ----------------------
__global__ void mixer_kernel(const float* __restrict__ c,
                             const float* __restrict__ Wm1, const float* __restrict__ bm1,
                             const float* __restrict__ Wm2, const float* __restrict__ bm2,
                             const float* __restrict__ Wr,  const float* __restrict__ br,
                             float* __restrict__ coeffs, float* __restrict__ ratio)
{
    __shared__ float cs[C_DIM];
    __shared__ float ms[C_DIM];
    __shared__ float red[C_DIM];
    __shared__ float lg[K_EXP];
    int t = blockIdx.x, tid = threadIdx.x;

    cs[tid] = c[t * C_DIM + tid];
    __syncthreads();

    float acc = bm1[tid];
#pragma unroll 8
    for (int i = 0; i < C_DIM; i++) acc += cs[i] * Wm1[i * C_DIM + tid];
    ms[tid] = silu_f(acc);
    red[tid] = cs[tid] * Wr[tid];
    __syncthreads();

    if (tid < K_EXP) {
        float l = bm2[tid];
#pragma unroll 8
        for (int i = 0; i < C_DIM; i++) l += ms[i] * Wm2[i * K_EXP + tid];
        lg[tid] = l;
    }
    for (int s = 128; s > 0; s >>= 1) {
        __syncthreads();
        if (tid < s) red[tid] += red[tid + s];
    }
    __syncthreads();

    if (tid == 0) {
        ratio[t] = red[0] + br[0];
        float mx = fmaxf(fmaxf(lg[0], lg[1]), fmaxf(lg[2], lg[3]));
        float e0 = __expf(lg[0] - mx), e1 = __expf(lg[1] - mx);
        float e2 = __expf(lg[2] - mx), e3 = __expf(lg[3] - mx);
        float inv = 1.0f / (e0 + e1 + e2 + e3);
        coeffs[t * 4 + 0] = e0 * inv;
        coeffs[t * 4 + 1] = e1 * inv;
        coeffs[t * 4 + 2] = e2 * inv;
        coeffs[t * 4 + 3] = e3 * inv;
    }
}

// -------------------- Monarch stage: per-(token,g) 32x32 GEMV --------------
template<int STAGE>
__global__ void monarch_kernel(const float* __restrict__ X,
                               const float* __restrict__ Mbuf,
                               float* __restrict__ out,
                               const float* __restrict__ ratio,
                               const float* __restrict__ biasor)
{
    __shared__ float xs[1024];
    int t = blockIdx.x;
    int tid = threadIdx.x;   // 256
#pragma unroll
    for (int i = tid; i < 1024; i += 256) xs[i] = X[t * 1024 + i];
    __syncthreads();

    int o = tid & 31, w = tid >> 5;
    const float* Mrow = Mbuf + (size_t)t * D_BIG;
#pragma unroll
    for (int gi = 0; gi < 4; gi++) {
        int g = w * 4 + gi;
        float acc = 0.0f;
        const float* mp = Mrow + g * 1024 + o;
#pragma unroll
        for (int i = 0; i < 32; i++) acc += xs[g * 32 + i] * mp[i * 32];
        if (STAGE == 1) {
            out[t * 1024 + o * 32 + g] = acc;           // transposed for stage 2
        } else {
            int idx = t * 1024 + g * 32 + o;
            out[idx] = acc * ratio[t] + biasor[idx];
        }
    }
}

// ---------------------------------------------------------------------------
extern "C" void kernel_launch(void* const* d_in, const int* in_sizes, int n_in,
                              void* d_out, int out_size)
{
    const float* x   = (const float*)d_in[0];
    const float* Wc  = (const float*)d_in[1];
    const float* bc  = (const float*)d_in[2];
    const float* W1a = (const float*)d_in[3];
    const float* b1a = (const float*)d_in[4];
    const float* W1b = (const float*)d_in[5];
    const float* b1b = (const float*)d_in[6];
    const float* W2a = (const float*)d_in[7];
    const float* b2a = (const float*)d_in[8];
    const float* W2b = (const float*)d_in[9];
    const float* b2b = (const float*)d_in[10];
    const float* Wm1 = (const float*)d_in[11];
    const float* bm1 = (const float*)d_in[12];
    const float* Wm2 = (const float*)d_in[13];
    const float* bm2 = (const float*)d_in[14];
    const float* Wb  = (const float*)d_in[15];
    const float* bb  = (const float*)d_in[16];
    const float* Wr  = (const float*)d_in[17];
    const float* br  = (const float*)d_in[18];
    float* out = (float*)d_out;

    float *p_c, *p_co, *p_ra, *p_bi, *p_x1, *p_M;
    __nv_bfloat16 *p_ahi, *p_alo;
    cudaGetSymbolAddress((void**)&p_c,   g_c);
    cudaGetSymbolAddress((void**)&p_ahi, g_Ahi);
    cudaGetSymbolAddress((void**)&p_alo, g_Alo);
    cudaGetSymbolAddress((void**)&p_co,  g_coeffs);
    cudaGetSymbolAddress((void**)&p_ra,  g_ratio);
    cudaGetSymbolAddress((void**)&p_bi,  g_biasor);
    cudaGetSymbolAddress((void**)&p_x1,  g_x1o);
    cudaGetSymbolAddress((void**)&p_M,   g_M);

    cudaFuncSetAttribute(bgemm_mma, cudaFuncAttributeMaxDynamicSharedMemorySize,
                         BGEMM_SMEM);

    // 1. c = silu(x @ Wc + bc)
    sgemm64<1><<<dim3(C_DIM / 64, T_TOK / 64, 1), 256>>>(
        x, Wc, p_c, IN_DIM, IN_DIM, C_DIM, C_DIM, bc, nullptr, 0, 0, 0,
        nullptr, nullptr);

    // 2. coeffs (softmax), ratio
    mixer_kernel<<<T_TOK, C_DIM>>>(p_c, Wm1, bm1, Wm2, bm2, Wr, br, p_co, p_ra);

    // 3. biasor = c @ Wb + bb
    sgemm64<0><<<dim3(OUT_DIM / 64, T_TOK / 64, 1), 256>>>(
        p_c, Wb, p_bi, C_DIM, C_DIM, OUT_DIM, OUT_DIM, bb, nullptr, 0, 0, 0,
        nullptr, nullptr);

    // 4. g1 = coeffs * silu(c @ W1a + b1a)  -> bf16 hi/lo
    sgemm64<2><<<dim3(C_DIM / 64, T_TOK / 64, K_EXP), 256>>>(
        p_c, W1a, nullptr, C_DIM, C_DIM, C_DIM, KC, b1a, p_co,
        C_DIM * C_DIM, C_DIM, C_DIM, p_ahi, p_alo);

    // 5. M1 = g1 @ W1b + coeffs @ b1b   (HMMA, 3x bf16 split)
    bgemm_mma<<<dim3(T_TOK / 128, D_BIG / 128), 256, BGEMM_SMEM>>>(
        p_ahi, p_alo, W1b, p_M, b1b, p_co);

    // 6. Monarch stage 1 (writes transposed)
    monarch_kernel<1><<<T_TOK, 256>>>(x, p_M, p_x1, nullptr, nullptr);

    // 7. g2 = coeffs * silu(c @ W2a + b2a)
    sgemm64<2><<<dim3(C_DIM / 64, T_TOK / 64, K_EXP), 256>>>(
        p_c, W2a, nullptr, C_DIM, C_DIM, C_DIM, KC, b2a, p_co,
        C_DIM * C_DIM, C_DIM, C_DIM, p_ahi, p_alo);

    // 8. M2 = g2 @ W2b + coeffs @ b2b
    bgemm_mma<<<dim3(T_TOK / 128, D_BIG / 128), 256, BGEMM_SMEM>>>(
        p_ahi, p_alo, W2b, p_M, b2b, p_co);

    // 9. Monarch stage 2 + final epilogue
    monarch_kernel<2><<<T_TOK, 256>>>(p_x1, p_M, out, p_ra, p_bi);
}

// round 6
// speedup vs baseline: 3.0036x; 1.8818x over previous
#include <cuda_runtime.h>
#include <cuda_bf16.h>
#include <cuda_fp16.h>
#include <cstdint>
#include <cstddef>

// ---------------------------------------------------------------------------
// HyperMoMixLinear on GB300 (sm_103a harness, PLAIN sm_103 ptx target).
// Big hypernet GEMMs (512x32768x1024, x2) on mma.sync fp16 with 2-term split:
//   A (activations) pre-split fp16 hi+lo (effectively exact, 22 mantissa bits),
//   W single fp16 operand. Output rel err ~1e-4 << 1e-3 threshold.
// ---------------------------------------------------------------------------

#define T_TOK 512
#define C_DIM 256
#define IN_DIM 1024
#define OUT_DIM 1024
#define K_EXP 4
#define D_BIG 32768
#define KC 1024   // K_EXP * C_DIM  == GEMM K

// -------------------- device scratch (no runtime allocation) ---------------
__device__ float g_c[T_TOK * C_DIM];
__device__ __half g_Ahi[T_TOK * KC];
__device__ __half g_Alo[T_TOK * KC];
__device__ float g_coeffs[T_TOK * K_EXP];
__device__ float g_ratio[T_TOK];
__device__ float g_biasor[T_TOK * OUT_DIM];
__device__ float g_x1o[T_TOK * OUT_DIM];
__device__ float g_M[(size_t)T_TOK * D_BIG];     // 64 MB scratch (M1 then M2)

__device__ __forceinline__ float silu_f(float v) {
    return v / (1.0f + __expf(-v));
}

__device__ __forceinline__ uint32_t smem_u32(const void* p) {
    uint32_t a;
    asm("{ .reg .u64 t; cvta.to.shared.u64 t, %1; cvt.u32.u64 %0, t; }"
        : "=r"(a) : "l"(p));
    return a;
}

#define CP_ASYNC16(dst, src) \
    asm volatile("cp.async.cg.shared.global [%0], [%1], 16;" \
                 :: "r"(dst), "l"(src) : "memory")
#define CP_COMMIT() asm volatile("cp.async.commit_group;" ::: "memory")
#define CP_WAIT0()  asm volatile("cp.async.wait_group 0;" ::: "memory")

#define LDSM4(r, addr) \
    asm volatile("ldmatrix.sync.aligned.m8n8.x4.shared.b16 {%0,%1,%2,%3}, [%4];" \
        : "=r"((r)[0]), "=r"((r)[1]), "=r"((r)[2]), "=r"((r)[3]) : "r"(addr))
#define LDSM4T(r, addr) \
    asm volatile("ldmatrix.sync.aligned.m8n8.x4.trans.shared.b16 {%0,%1,%2,%3}, [%4];" \
        : "=r"((r)[0]), "=r"((r)[1]), "=r"((r)[2]), "=r"((r)[3]) : "r"(addr))

#define MMA_F16(d, a, b0v, b1v) \
    asm volatile("mma.sync.aligned.m16n8k16.row.col.f32.f16.f16.f32 " \
        "{%0,%1,%2,%3}, {%4,%5,%6,%7}, {%8,%9}, {%0,%1,%2,%3};" \
        : "+f"((d)[0]), "+f"((d)[1]), "+f"((d)[2]), "+f"((d)[3]) \
        : "r"((a)[0]), "r"((a)[1]), "r"((a)[2]), "r"((a)[3]), \
          "r"(b0v), "r"(b1v))

__device__ __forceinline__ uint32_t pack_f16x2(float a, float b) {
    __half2 h = __floats2half2_rn(a, b);
    return *(uint32_t*)&h;
}

// -------------------- small GEMM: 64x64x16 tiles, 4x4 per thread -----------
// EPI 0: out = acc + bias[n]          (fp32)
// EPI 1: out = silu(acc + bias[n])    (fp32)
// EPI 2: coeffs[m,kz]*silu(acc+bias)  -> fp16 hi/lo split outputs
template<int EPI>
__global__ void sgemm64(const float* __restrict__ A, const float* __restrict__ B,
                        float* __restrict__ Cmat,
                        int Kd, int lda, int ldb, int ldc,
                        const float* __restrict__ bias,
                        const float* __restrict__ coeffs,
                        int b_zstride, int bias_zstride, int col_zstride,
                        __half* __restrict__ ghi,
                        __half* __restrict__ glo)
{
    const int BM = 64, BN = 64, BK = 16;
    __shared__ float As[BK][BM];
    __shared__ float Bs[BK][BN];
    int tid = threadIdx.x;
    int kz = blockIdx.z;
    B += (long)kz * b_zstride;
    bias += kz * bias_zstride;
    int m0 = blockIdx.y * BM;
    int n0 = blockIdx.x * BN;
    int tx = tid % 16, ty = tid / 16;
    int arow = tid / 4, aq = tid % 4;
    int brow = tid / 16, bq = tid % 16;
    float acc[4][4] = {};

    for (int k0 = 0; k0 < Kd; k0 += BK) {
        float4 av = *(const float4*)&A[(m0 + arow) * lda + k0 + aq * 4];
        As[aq * 4 + 0][arow] = av.x;
        As[aq * 4 + 1][arow] = av.y;
        As[aq * 4 + 2][arow] = av.z;
        As[aq * 4 + 3][arow] = av.w;
        *(float4*)&Bs[brow][bq * 4] =
            *(const float4*)&B[(k0 + brow) * ldb + n0 + bq * 4];
        __syncthreads();
#pragma unroll
        for (int k = 0; k < BK; k++) {
            float a[4], b[4];
#pragma unroll
            for (int i = 0; i < 4; i++) a[i] = As[k][ty * 4 + i];
#pragma unroll
            for (int j = 0; j < 4; j++) b[j] = Bs[k][tx * 4 + j];
#pragma unroll
            for (int i = 0; i < 4; i++)
#pragma unroll
                for (int j = 0; j < 4; j++) acc[i][j] += a[i] * b[j];
        }
        __syncthreads();
    }

#pragma unroll
    for (int i = 0; i < 4; i++) {
        int m = m0 + ty * 4 + i;
        float cf = 1.0f;
        if (EPI == 2) cf = coeffs[m * K_EXP + kz];
#pragma unroll
        for (int j = 0; j < 4; j++) {
            int n = n0 + tx * 4 + j;
            float v = acc[i][j] + bias[n];
            if (EPI == 1) v = silu_f(v);
            if (EPI == 2) {
                v = cf * silu_f(v);
                int idx = m * ldc + kz * col_zstride + n;
                __half h = __float2half(v);
                ghi[idx] = h;
                glo[idx] = __float2half(v - __half2float(h));
            } else {
                Cmat[m * ldc + kz * col_zstride + n] = v;
            }
        }
    }
}

// -------------------- big GEMM on mma.sync (HMMA fp16, 2-term split) -------
// C[512,32768] = A[512,1024] @ W[1024,32768] + coeffs@bB
// A pre-split fp16 hi/lo in gmem; W fp32, converted to single fp16 in-kernel.
// CTA tile 128x128, BK=32, double-buffered smem, 8 warps of 64x32.
//
// smem per stage (24 KB):
//   A: 128 rows x 128 B  (hi bytes [0,64), lo [64,128), swizzled)   16 KB
//   B: 32 k-rows x 256 B (fp16, swizzled)                            8 KB
__global__ void __launch_bounds__(256, 1) bgemm_mma(
    const __half* __restrict__ Ahi, const __half* __restrict__ Alo,
    const float* __restrict__ W,
    float* __restrict__ C,
    const float* __restrict__ bB,      // [K_EXP, D_BIG]
    const float* __restrict__ coeffs)  // [T, K_EXP]
{
    extern __shared__ __align__(128) char smem[];
    const uint32_t sbase = smem_u32(smem);
    const int tid = threadIdx.x, wid = tid >> 5, lane = tid & 31;
    const int m0 = blockIdx.x * 128, n0 = blockIdx.y * 128;
    const int warp_m = wid & 1, warp_n = wid >> 1;   // 2 x 4 warps

    const uint32_t STG = 24576;   // bytes per stage
    const uint32_t BOFF = 16384;  // B plane offset within stage

    float acc[4][4][4] = {};

    // ---- A cp.async per-thread geometry (4 x 16B per iter) ----
    const int a_m_lo = tid >> 2;           // + (i&1)*64
    const int a_gq = tid & 3;
    const uint32_t a_xor = ((uint32_t)(a_m_lo & 7)) << 4;
    // ---- B per-thread geometry (4 x float4 per iter) ----
    const int b_krow = tid >> 5;           // + i*8
    const int b_c4 = tid & 31;
    const uint32_t b_sto = ((uint32_t)(b_c4 * 8)) ^ (((uint32_t)b_krow) << 4);

    float bf[16];                           // prefetched W values

    // ---- warp ldmatrix geometry ----
    const int aRow = warp_m * 64 + (lane & 15);
    const uint32_t axor = ((uint32_t)(aRow & 7)) << 4;
    const uint32_t aKhalf = ((lane >> 4) & 1) * 16;
    uint32_t kOffA[2][2];                  // [sel][ks16]
#pragma unroll
    for (int sel = 0; sel < 2; sel++)
#pragma unroll
        for (int ks = 0; ks < 2; ks++)
            kOffA[sel][ks] = ((uint32_t)(sel * 64 + ks * 32) + aKhalf) ^ axor;
    const uint32_t aBase = (uint32_t)aRow * 128;

    const int kLoc = (lane & 7) | (((lane >> 3) & 1) << 3);
    const uint32_t bxor = ((uint32_t)(kLoc & 7)) << 4;
    const uint32_t bBase = (uint32_t)kLoc * 256;
    uint32_t nbp[2];
#pragma unroll
    for (int p = 0; p < 2; p++)
        nbp[p] = ((uint32_t)((warp_n * 32 + p * 16 + ((lane >> 4) & 1) * 8) * 2)) ^ bxor;

    auto issueA = [&](int it, int buf) {
        uint32_t sA = sbase + buf * STG;
        int k0 = it * 32;
#pragma unroll
        for (int i = 0; i < 4; i++) {
            int sel = i >> 1;
            int m = a_m_lo + (i & 1) * 64;
            const __half* src =
                (sel ? Alo : Ahi) + (size_t)(m0 + m) * KC + k0 + a_gq * 8;
            uint32_t dst = sA + (uint32_t)m * 128 +
                           (((uint32_t)(sel * 64 + a_gq * 16)) ^ a_xor);
            CP_ASYNC16(dst, src);
        }
        CP_COMMIT();
    };
    auto loadB = [&](int it) {
        int k0 = it * 32;
#pragma unroll
        for (int i = 0; i < 4; i++) {
            float4 v = *(const float4*)(W + (size_t)(k0 + b_krow + i * 8) * D_BIG
                                          + n0 + b_c4 * 4);
            bf[i * 4 + 0] = v.x; bf[i * 4 + 1] = v.y;
            bf[i * 4 + 2] = v.z; bf[i * 4 + 3] = v.w;
        }
    };
    auto storeB = [&](int buf) {
#pragma unroll
        for (int i = 0; i < 4; i++) {
            uint2 hv;
            hv.x = pack_f16x2(bf[i * 4 + 0], bf[i * 4 + 1]);
            hv.y = pack_f16x2(bf[i * 4 + 2], bf[i * 4 + 3]);
            uint32_t off = (uint32_t)(b_krow + i * 8) * 256 + b_sto;
            *(uint2*)(smem + (buf * STG + BOFF) + off) = hv;
        }
    };

    // ---- preamble: stage 0 ----
    issueA(0, 0);
    loadB(0);
    storeB(0);
    CP_WAIT0();
    __syncthreads();

    // ---- main loop ----
    for (int it = 0; it < 32; ++it) {
        int cur = it & 1;
        if (it < 31) { issueA(it + 1, cur ^ 1); loadB(it + 1); }

        uint32_t sA = sbase + cur * STG;
        uint32_t sB = sA + BOFF;
#pragma unroll
        for (int ks = 0; ks < 2; ks++) {
            uint32_t ah[4][4], al[4][4], bb[2][4];
#pragma unroll
            for (int mt = 0; mt < 4; mt++)
                LDSM4(ah[mt], sA + aBase + mt * 2048 + kOffA[0][ks]);
#pragma unroll
            for (int p = 0; p < 2; p++)
                LDSM4T(bb[p], sB + ks * 4096 + bBase + nbp[p]);
            // hi * B
#pragma unroll
            for (int mt = 0; mt < 4; mt++)
#pragma unroll
                for (int nt = 0; nt < 4; nt++)
                    MMA_F16(acc[mt][nt], ah[mt],
                            bb[nt >> 1][(nt & 1) * 2], bb[nt >> 1][(nt & 1) * 2 + 1]);
            // lo * B
#pragma unroll
            for (int mt = 0; mt < 4; mt++)
                LDSM4(al[mt], sA + aBase + mt * 2048 + kOffA[1][ks]);
#pragma unroll
            for (int mt = 0; mt < 4; mt++)
#pragma unroll
                for (int nt = 0; nt < 4; nt++)
                    MMA_F16(acc[mt][nt], al[mt],
                            bb[nt >> 1][(nt & 1) * 2], bb[nt >> 1][(nt & 1) * 2 + 1]);
        }

        if (it < 31) { CP_WAIT0(); storeB(cur ^ 1); }
        __syncthreads();
    }

    // ---- epilogue: direct stores with mixed-expert bias ----
    const int mw = m0 + warp_m * 64;
    const int nw = n0 + warp_n * 32;
    const int row = lane >> 2, col = (lane & 3) * 2;
#pragma unroll
    for (int nt = 0; nt < 4; nt++) {
        int n = nw + nt * 8 + col;
        float bv[4][2];
#pragma unroll
        for (int e = 0; e < 4; e++) {
            bv[e][0] = bB[(size_t)e * D_BIG + n];
            bv[e][1] = bB[(size_t)e * D_BIG + n + 1];
        }
#pragma unroll
        for (int mt = 0; mt < 4; mt++) {
            int m = mw + mt * 16 + row;
            float4 c0 = *(const float4*)(coeffs + m * 4);
            float4 c1 = *(const float4*)(coeffs + (m + 8) * 4);
            float bias00 = c0.x * bv[0][0] + c0.y * bv[1][0] + c0.z * bv[2][0] + c0.w * bv[3][0];
            float bias01 = c0.x * bv[0][1] + c0.y * bv[1][1] + c0.z * bv[2][1] + c0.w * bv[3][1];
            float bias10 = c1.x * bv[0][0] + c1.y * bv[1][0] + c1.z * bv[2][0] + c1.w * bv[3][0];
            float bias11 = c1.x * bv[0][1] + c1.y * bv[1][1] + c1.z * bv[2][1] + c1.w * bv[3][1];
            float2 o0 = { acc[mt][nt][0] + bias00, acc[mt][nt][1] + bias01 };
            float2 o1 = { acc[mt][nt][2] + bias10, acc[mt][nt][3] + bias11 };
            *(float2*)(C + (size_t)m * D_BIG + n) = o0;
            *(float2*)(C + (size_t)(m + 8) * D_BIG + n) = o1;
        }
    }
}
#define BGEMM_SMEM (2 * 24576)

// -------------------- mixer: coeffs + ratio per token ----------------------
__global__ void mixer_kernel(const float* __restrict__ c,
                             const float* __restrict__ Wm1, const float* __restrict__ bm1,
                             const float* __restrict__ Wm2, const float* __restrict__ bm2,
                             const float* __restrict__ Wr,  const float* __restrict__ br,
                             float* __restrict__ coeffs, float* __restrict__ ratio)
{
    __shared__ float cs[C_DIM];
    __shared__ float ms[C_DIM];
    __shared__ float red[C_DIM];
    __shared__ float lg[K_EXP];
    int t = blockIdx.x, tid = threadIdx.x;

    cs[tid] = c[t * C_DIM + tid];
    __syncthreads();

    float acc = bm1[tid];
#pragma unroll 8
    for (int i = 0; i < C_DIM; i++) acc += cs[i] * Wm1[i * C_DIM + tid];
    ms[tid] = silu_f(acc);
    red[tid] = cs[tid] * Wr[tid];
    __syncthreads();

    if (tid < K_EXP) {
        float l = bm2[tid];
#pragma unroll 8
        for (int i = 0; i < C_DIM; i++) l += ms[i] * Wm2[i * K_EXP + tid];
        lg[tid] = l;
    }
    for (int s = 128; s > 0; s >>= 1) {
        __syncthreads();
        if (tid < s) red[tid] += red[tid + s];
    }
    __syncthreads();

    if (tid == 0) {
        ratio[t] = red[0] + br[0];
        float mx = fmaxf(fmaxf(lg[0], lg[1]), fmaxf(lg[2], lg[3]));
        float e0 = __expf(lg[0] - mx), e1 = __expf(lg[1] - mx);
        float e2 = __expf(lg[2] - mx), e3 = __expf(lg[3] - mx);
        float inv = 1.0f / (e0 + e1 + e2 + e3);
        coeffs[t * 4 + 0] = e0 * inv;
        coeffs[t * 4 + 1] = e1 * inv;
        coeffs[t * 4 + 2] = e2 * inv;
        coeffs[t * 4 + 3] = e3 * inv;
    }
}

// -------------------- Monarch stage: per-(token,g) 32x32 GEMV --------------
template<int STAGE>
__global__ void monarch_kernel(const float* __restrict__ X,
                               const float* __restrict__ Mbuf,
                               float* __restrict__ out,
                               const float* __restrict__ ratio,
                               const float* __restrict__ biasor)
{
    __shared__ float xs[1024];
    int t = blockIdx.x;
    int tid = threadIdx.x;   // 256
#pragma unroll
    for (int i = tid; i < 1024; i += 256) xs[i] = X[t * 1024 + i];
    __syncthreads();

    int o = tid & 31, w = tid >> 5;
    const float* Mrow = Mbuf + (size_t)t * D_BIG;
#pragma unroll
    for (int gi = 0; gi < 4; gi++) {
        int g = w * 4 + gi;
        float acc = 0.0f;
        const float* mp = Mrow + g * 1024 + o;
#pragma unroll
        for (int i = 0; i < 32; i++) acc += xs[g * 32 + i] * mp[i * 32];
        if (STAGE == 1) {
            out[t * 1024 + o * 32 + g] = acc;           // transposed for stage 2
        } else {
            int idx = t * 1024 + g * 32 + o;
            out[idx] = acc * ratio[t] + biasor[idx];
        }
    }
}

// ---------------------------------------------------------------------------
extern "C" void kernel_launch(void* const* d_in, const int* in_sizes, int n_in,
                              void* d_out, int out_size)
{
    const float* x   = (const float*)d_in[0];
    const float* Wc  = (const float*)d_in[1];
    const float* bc  = (const float*)d_in[2];
    const float* W1a = (const float*)d_in[3];
    const float* b1a = (const float*)d_in[4];
    const float* W1b = (const float*)d_in[5];
    const float* b1b = (const float*)d_in[6];
    const float* W2a = (const float*)d_in[7];
    const float* b2a = (const float*)d_in[8];
    const float* W2b = (const float*)d_in[9];
    const float* b2b = (const float*)d_in[10];
    const float* Wm1 = (const float*)d_in[11];
    const float* bm1 = (const float*)d_in[12];
    const float* Wm2 = (const float*)d_in[13];
    const float* bm2 = (const float*)d_in[14];
    const float* Wb  = (const float*)d_in[15];
    const float* bb  = (const float*)d_in[16];
    const float* Wr  = (const float*)d_in[17];
    const float* br  = (const float*)d_in[18];
    float* out = (float*)d_out;

    float *p_c, *p_co, *p_ra, *p_bi, *p_x1, *p_M;
    __half *p_ahi, *p_alo;
    cudaGetSymbolAddress((void**)&p_c,   g_c);
    cudaGetSymbolAddress((void**)&p_ahi, g_Ahi);
    cudaGetSymbolAddress((void**)&p_alo, g_Alo);
    cudaGetSymbolAddress((void**)&p_co,  g_coeffs);
    cudaGetSymbolAddress((void**)&p_ra,  g_ratio);
    cudaGetSymbolAddress((void**)&p_bi,  g_biasor);
    cudaGetSymbolAddress((void**)&p_x1,  g_x1o);
    cudaGetSymbolAddress((void**)&p_M,   g_M);

    cudaFuncSetAttribute(bgemm_mma, cudaFuncAttributeMaxDynamicSharedMemorySize,
                         BGEMM_SMEM);

    // 1. c = silu(x @ Wc + bc)
    sgemm64<1><<<dim3(C_DIM / 64, T_TOK / 64, 1), 256>>>(
        x, Wc, p_c, IN_DIM, IN_DIM, C_DIM, C_DIM, bc, nullptr, 0, 0, 0,
        nullptr, nullptr);

    // 2. coeffs (softmax), ratio
    mixer_kernel<<<T_TOK, C_DIM>>>(p_c, Wm1, bm1, Wm2, bm2, Wr, br, p_co, p_ra);

    // 3. biasor = c @ Wb + bb
    sgemm64<0><<<dim3(OUT_DIM / 64, T_TOK / 64, 1), 256>>>(
        p_c, Wb, p_bi, C_DIM, C_DIM, OUT_DIM, OUT_DIM, bb, nullptr, 0, 0, 0,
        nullptr, nullptr);

    // 4. g1 = coeffs * silu(c @ W1a + b1a)  -> fp16 hi/lo
    sgemm64<2><<<dim3(C_DIM / 64, T_TOK / 64, K_EXP), 256>>>(
        p_c, W1a, nullptr, C_DIM, C_DIM, C_DIM, KC, b1a, p_co,
        C_DIM * C_DIM, C_DIM, C_DIM, p_ahi, p_alo);

    // 5. M1 = g1 @ W1b + coeffs @ b1b   (HMMA fp16, 2-term split)
    bgemm_mma<<<dim3(T_TOK / 128, D_BIG / 128), 256, BGEMM_SMEM>>>(
        p_ahi, p_alo, W1b, p_M, b1b, p_co);

    // 6. Monarch stage 1 (writes transposed)
    monarch_kernel<1><<<T_TOK, 256>>>(x, p_M, p_x1, nullptr, nullptr);

    // 7. g2 = coeffs * silu(c @ W2a + b2a)
    sgemm64<2><<<dim3(C_DIM / 64, T_TOK / 64, K_EXP), 256>>>(
        p_c, W2a, nullptr, C_DIM, C_DIM, C_DIM, KC, b2a, p_co,
        C_DIM * C_DIM, C_DIM, C_DIM, p_ahi, p_alo);

    // 8. M2 = g2 @ W2b + coeffs @ b2b
    bgemm_mma<<<dim3(T_TOK / 128, D_BIG / 128), 256, BGEMM_SMEM>>>(
        p_ahi, p_alo, W2b, p_M, b2b, p_co);

    // 9. Monarch stage 2 + final epilogue
    monarch_kernel<2><<<T_TOK, 256>>>(p_x1, p_M, out, p_ra, p_bi);
}

// round 7
// speedup vs baseline: 3.0224x; 1.0063x over previous
#include <cuda_runtime.h>
#include <cuda_bf16.h>
#include <cuda_fp16.h>
#include <cstdint>
#include <cstddef>

// ---------------------------------------------------------------------------
// HyperMoMixLinear on GB300 (sm_103a harness, PLAIN sm_103 ptx target).
// Big hypernet GEMMs run on mma.sync fp16 (1-term; precision headroom
// verified: 2-term measured 1.0e-5 vs 1e-3 budget). The per-token Monarch
// contraction is FUSED into the GEMM epilogue: M1/M2 (64 MB each) are never
// materialized. CTA = (128 tokens) x (one Monarch group g = 1024 cols),
// looping 8 N-subtiles; warp_n == local-i, partials accumulate in smem
// planes, reduced at CTA end. No atomics -> deterministic.
// ---------------------------------------------------------------------------

#define T_TOK 512
#define C_DIM 256
#define IN_DIM 1024
#define OUT_DIM 1024
#define K_EXP 4
#define D_BIG 32768
#define KC 1024   // K_EXP * C_DIM  == GEMM K

// -------------------- device scratch (no runtime allocation) ---------------
__device__ float g_c[T_TOK * C_DIM];
__device__ __half g_A16[T_TOK * KC];
__device__ float g_coeffs[T_TOK * K_EXP];
__device__ float g_ratio[T_TOK];
__device__ float g_biasor[T_TOK * OUT_DIM];
__device__ float g_x1oT[T_TOK * OUT_DIM];   // stage-1 result, transposed layout

__device__ __forceinline__ float silu_f(float v) {
    return v / (1.0f + __expf(-v));
}

__device__ __forceinline__ uint32_t smem_u32(const void* p) {
    uint32_t a;
    asm("{ .reg .u64 t; cvta.to.shared.u64 t, %1; cvt.u32.u64 %0, t; }"
        : "=r"(a) : "l"(p));
    return a;
}

#define CP_ASYNC16(dst, src) \
    asm volatile("cp.async.cg.shared.global [%0], [%1], 16;" \
                 :: "r"(dst), "l"(src) : "memory")
#define CP_COMMIT() asm volatile("cp.async.commit_group;" ::: "memory")
#define CP_WAIT0()  asm volatile("cp.async.wait_group 0;" ::: "memory")

#define LDSM4(r, addr) \
    asm volatile("ldmatrix.sync.aligned.m8n8.x4.shared.b16 {%0,%1,%2,%3}, [%4];" \
        : "=r"((r)[0]), "=r"((r)[1]), "=r"((r)[2]), "=r"((r)[3]) : "r"(addr))
#define LDSM4T(r, addr) \
    asm volatile("ldmatrix.sync.aligned.m8n8.x4.trans.shared.b16 {%0,%1,%2,%3}, [%4];" \
        : "=r"((r)[0]), "=r"((r)[1]), "=r"((r)[2]), "=r"((r)[3]) : "r"(addr))

#define MMA_F16(d, a, b0v, b1v) \
    asm volatile("mma.sync.aligned.m16n8k16.row.col.f32.f16.f16.f32 " \
        "{%0,%1,%2,%3}, {%4,%5,%6,%7}, {%8,%9}, {%0,%1,%2,%3};" \
        : "+f"((d)[0]), "+f"((d)[1]), "+f"((d)[2]), "+f"((d)[3]) \
        : "r"((a)[0]), "r"((a)[1]), "r"((a)[2]), "r"((a)[3]), \
          "r"(b0v), "r"(b1v))

__device__ __forceinline__ uint32_t pack_f16x2(float a, float b) {
    __half2 h = __floats2half2_rn(a, b);
    return *(uint32_t*)&h;
}

// -------------------- small GEMM: 64x64x16 tiles, 4x4 per thread -----------
// EPI 0: out = acc + bias[n]          (fp32)
// EPI 1: out = silu(acc + bias[n])    (fp32)
// EPI 2: coeffs[m,kz]*silu(acc+bias)  -> fp16 output
template<int EPI>
__global__ void sgemm64(const float* __restrict__ A, const float* __restrict__ B,
                        float* __restrict__ Cmat,
                        int Kd, int lda, int ldb, int ldc,
                        const float* __restrict__ bias,
                        const float* __restrict__ coeffs,
                        int b_zstride, int bias_zstride, int col_zstride,
                        __half* __restrict__ g16)
{
    const int BM = 64, BN = 64, BK = 16;
    __shared__ float As[BK][BM];
    __shared__ float Bs[BK][BN];
    int tid = threadIdx.x;
    int kz = blockIdx.z;
    B += (long)kz * b_zstride;
    bias += kz * bias_zstride;
    int m0 = blockIdx.y * BM;
    int n0 = blockIdx.x * BN;
    int tx = tid % 16, ty = tid / 16;
    int arow = tid / 4, aq = tid % 4;
    int brow = tid / 16, bq = tid % 16;
    float acc[4][4] = {};

    for (int k0 = 0; k0 < Kd; k0 += BK) {
        float4 av = *(const float4*)&A[(m0 + arow) * lda + k0 + aq * 4];
        As[aq * 4 + 0][arow] = av.x;
        As[aq * 4 + 1][arow] = av.y;
        As[aq * 4 + 2][arow] = av.z;
        As[aq * 4 + 3][arow] = av.w;
        *(float4*)&Bs[brow][bq * 4] =
            *(const float4*)&B[(k0 + brow) * ldb + n0 + bq * 4];
        __syncthreads();
#pragma unroll
        for (int k = 0; k < BK; k++) {
            float a[4], b[4];
#pragma unroll
            for (int i = 0; i < 4; i++) a[i] = As[k][ty * 4 + i];
#pragma unroll
            for (int j = 0; j < 4; j++) b[j] = Bs[k][tx * 4 + j];
#pragma unroll
            for (int i = 0; i < 4; i++)
#pragma unroll
                for (int j = 0; j < 4; j++) acc[i][j] += a[i] * b[j];
        }
        __syncthreads();
    }

#pragma unroll
    for (int i = 0; i < 4; i++) {
        int m = m0 + ty * 4 + i;
        float cf = 1.0f;
        if (EPI == 2) cf = coeffs[m * K_EXP + kz];
#pragma unroll
        for (int j = 0; j < 4; j++) {
            int n = n0 + tx * 4 + j;
            float v = acc[i][j] + bias[n];
            if (EPI == 1) v = silu_f(v);
            if (EPI == 2) {
                v = cf * silu_f(v);
                g16[m * ldc + kz * col_zstride + n] = __float2half(v);
            } else {
                Cmat[m * ldc + kz * col_zstride + n] = v;
            }
        }
    }
}

// -------------------- fused big GEMM + Monarch contraction -----------------
// For Monarch group g (blockIdx.y) and 128-token block (blockIdx.x):
//   M[t, g*1024 + i*32 + o] = (g16[t] @ W)[col] + sum_e coeffs[t,e]*bB[e,col]
//   part[t, o] = sum_i xs[t, i] * M[...]
// STAGE 1: outp[t, o*32+g] = part      (transposed -> stage-2 input layout)
// STAGE 2: outp[t, g*32+o] = part * ratio[t] + biasor[t, g*32+o]
// N-subtiles j=0..7 (i-groups of 4), warp_n == local i. Flat (j,it) pipeline.
//
// smem: xs [128][32] fp32 (16 KB) | planes [4][128][33] fp32 (67.6 KB)
//       | 2 stages x (A 128x128B fp16 + B 64x256B fp16) (64 KB)
#define XS_OFF 0
#define PL_OFF 16384
#define PLW 33
#define STG_OFF (16384 + 4 * 128 * PLW * 4)        // 83968
#define STG_SZ 32768
#define B_OFF 16384
#define FUSED_SMEM (STG_OFF + 2 * STG_SZ)          // 149504

template<int STAGE>
__global__ void __launch_bounds__(256, 1) bgemm_fused(
    const __half* __restrict__ A16,
    const float* __restrict__ W,
    const float* __restrict__ xsrc,    // [T,1024]: x (stage1) / x1oT (stage2)
    float* __restrict__ outp,
    const float* __restrict__ bB,      // [K_EXP, D_BIG]
    const float* __restrict__ coeffs,  // [T, K_EXP]
    const float* __restrict__ ratio,   // [T]
    const float* __restrict__ biasor)  // [T, OUT]
{
    extern __shared__ __align__(128) char smem[];
    float* xs = (float*)(smem + XS_OFF);             // [128][32]
    float* plane = (float*)(smem + PL_OFF);          // [4][128][PLW]
    const uint32_t sbase = smem_u32(smem + STG_OFF);

    const int tid = threadIdx.x, wid = tid >> 5, lane = tid & 31;
    const int m0 = blockIdx.x * 128;
    const int g = blockIdx.y;
    const int warp_m = wid & 1, warp_n = wid >> 1;

    // ---- init: xs + zero planes ----
    {
        int t = tid >> 1, h = tid & 1;
        const float* src = xsrc + (size_t)(m0 + t) * 1024 + g * 32 + h * 16;
        float* dst = xs + t * 32 + h * 16;
#pragma unroll
        for (int q = 0; q < 4; q++)
            *(float4*)(dst + q * 4) = *(const float4*)(src + q * 4);
    }
    for (int i = tid; i < 4 * 128 * PLW; i += 256) plane[i] = 0.0f;

    // ---- A cp.async geometry: 4 x 16B per thread per stage (k=64/stage) ----
    const int a_m = tid >> 2;           // + (i&1)*64
    const int a_q = tid & 3;            // + (i>>1)*4
    // ---- B ld/convert/st geometry ----
    const int b_kr = tid >> 5;          // row within 8-group
    const int b_c4 = tid & 31;          // 4-float col group
    const uint32_t b_sto = ((uint32_t)(b_c4 * 8)) ^ (((uint32_t)b_kr) << 4);

    // ---- warp ldmatrix geometry (identical to validated r5 kernel) ----
    const int aRow = warp_m * 64 + (lane & 15);
    const uint32_t axor = ((uint32_t)(aRow & 7)) << 4;
    const uint32_t aKhalf = ((lane >> 4) & 1) * 16;
    uint32_t kOffA[2][2];
#pragma unroll
    for (int sel = 0; sel < 2; sel++)
#pragma unroll
        for (int ks = 0; ks < 2; ks++)
            kOffA[sel][ks] = ((uint32_t)(sel * 64 + ks * 32) + aKhalf) ^ axor;
    const uint32_t aBase = (uint32_t)aRow * 128;

    const int kLoc = (lane & 7) | (((lane >> 3) & 1) << 3);
    const uint32_t bxor = ((uint32_t)(kLoc & 7)) << 4;
    const uint32_t bBase = (uint32_t)kLoc * 256;
    uint32_t nbp[2];
#pragma unroll
    for (int p = 0; p < 2; p++)
        nbp[p] = ((uint32_t)((warp_n * 32 + p * 16 + ((lane >> 4) & 1) * 8) * 2)) ^ bxor;

    float bf[16];
    float acc[4][4][4] = {};

    auto issueA = [&](int it, int buf) {
        uint32_t sA = sbase + buf * STG_SZ;
        int k0 = it * 64;
#pragma unroll
        for (int i = 0; i < 4; i++) {
            int m = a_m + (i & 1) * 64;
            int q = a_q + (i >> 1) * 4;
            const __half* src = A16 + (size_t)(m0 + m) * KC + k0 + q * 8;
            uint32_t dst = sA + (uint32_t)m * 128 +
                           (((uint32_t)(q * 16)) ^ (((uint32_t)(m & 7)) << 4));
            CP_ASYNC16(dst, src);
        }
        CP_COMMIT();
    };
    auto loadBh = [&](int j, int it, int h) {
        int k0 = it * 64;
        size_t ncol = (size_t)g * 1024 + j * 128 + b_c4 * 4;
#pragma unroll
        for (int i = 0; i < 4; i++) {
            float4 v = *(const float4*)(W + (size_t)(k0 + h * 32 + b_kr + i * 8) * D_BIG + ncol);
            bf[i * 4 + 0] = v.x; bf[i * 4 + 1] = v.y;
            bf[i * 4 + 2] = v.z; bf[i * 4 + 3] = v.w;
        }
    };
    auto storeBh = [&](int h, int buf) {
#pragma unroll
        for (int i = 0; i < 4; i++) {
            uint2 hv;
            hv.x = pack_f16x2(bf[i * 4 + 0], bf[i * 4 + 1]);
            hv.y = pack_f16x2(bf[i * 4 + 2], bf[i * 4 + 3]);
            uint32_t off = (uint32_t)(h * 32 + b_kr + i * 8) * 256 + b_sto;
            *(uint2*)(smem + STG_OFF + buf * STG_SZ + B_OFF + off) = hv;
        }
    };
    auto mmaSel = [&](int sel, int buf) {
        uint32_t sA = sbase + buf * STG_SZ;
        uint32_t sB = sA + B_OFF + sel * 8192;
#pragma unroll
        for (int ks = 0; ks < 2; ks++) {
            uint32_t ah[4][4], bb[2][4];
#pragma unroll
            for (int mt = 0; mt < 4; mt++)
                LDSM4(ah[mt], sA + aBase + mt * 2048 + kOffA[sel][ks]);
#pragma unroll
            for (int p = 0; p < 2; p++)
                LDSM4T(bb[p], sB + ks * 4096 + bBase + nbp[p]);
#pragma unroll
            for (int mt = 0; mt < 4; mt++)
#pragma unroll
                for (int nt = 0; nt < 4; nt++)
                    MMA_F16(acc[mt][nt], ah[mt],
                            bb[nt >> 1][(nt & 1) * 2], bb[nt >> 1][(nt & 1) * 2 + 1]);
        }
    };

    // ---- preamble (j=0, it=0) ----
    issueA(0, 0);
    loadBh(0, 0, 0); storeBh(0, 0);
    loadBh(0, 0, 1); storeBh(1, 0);
    CP_WAIT0();
    __syncthreads();

    const int row = lane >> 2, colq = (lane & 3) * 2;
    float* myplane = plane + warp_n * (128 * PLW);

    // ---- flat (j, it) main loop: 128 iterations ----
    for (int ii = 0; ii < 128; ++ii) {
        int it = ii & 15;
        int cur = ii & 1, nxt = cur ^ 1;
        int jn = (ii + 1) >> 4, itn = (ii + 1) & 15;

        if (ii < 127) { issueA(itn, nxt); loadBh(jn, itn, 0); }
        mmaSel(0, cur);
        if (ii < 127) { storeBh(0, nxt); loadBh(jn, itn, 1); }
        mmaSel(1, cur);
        if (ii < 127) { storeBh(1, nxt); CP_WAIT0(); }

        if (it == 15) {
            // ---- epilogue for j = ii>>4: contract this n-subtile ----
            int j = ii >> 4;
            int xi = j * 4 + warp_n;
            size_t cbase = (size_t)g * 1024 + (size_t)j * 128;
#pragma unroll
            for (int nt = 0; nt < 4; nt++) {
                int nl = warp_n * 32 + nt * 8 + colq;
                int o = nt * 8 + colq;
                float bv[K_EXP][2];
#pragma unroll
                for (int e = 0; e < K_EXP; e++) {
                    bv[e][0] = bB[(size_t)e * D_BIG + cbase + nl];
                    bv[e][1] = bB[(size_t)e * D_BIG + cbase + nl + 1];
                }
#pragma unroll
                for (int mt = 0; mt < 4; mt++) {
                    int t0 = warp_m * 64 + mt * 16 + row;
                    int t1 = t0 + 8;
                    float4 c0 = *(const float4*)(coeffs + (m0 + t0) * 4);
                    float4 c1 = *(const float4*)(coeffs + (m0 + t1) * 4);
                    float b00 = c0.x * bv[0][0] + c0.y * bv[1][0] + c0.z * bv[2][0] + c0.w * bv[3][0];
                    float b01 = c0.x * bv[0][1] + c0.y * bv[1][1] + c0.z * bv[2][1] + c0.w * bv[3][1];
                    float b10 = c1.x * bv[0][0] + c1.y * bv[1][0] + c1.z * bv[2][0] + c1.w * bv[3][0];
                    float b11 = c1.x * bv[0][1] + c1.y * bv[1][1] + c1.z * bv[2][1] + c1.w * bv[3][1];
                    float x0 = xs[t0 * 32 + xi];
                    float x1 = xs[t1 * 32 + xi];
                    myplane[t0 * PLW + o]     += (acc[mt][nt][0] + b00) * x0;
                    myplane[t0 * PLW + o + 1] += (acc[mt][nt][1] + b01) * x0;
                    myplane[t1 * PLW + o]     += (acc[mt][nt][2] + b10) * x1;
                    myplane[t1 * PLW + o + 1] += (acc[mt][nt][3] + b11) * x1;
                    acc[mt][nt][0] = 0.0f; acc[mt][nt][1] = 0.0f;
                    acc[mt][nt][2] = 0.0f; acc[mt][nt][3] = 0.0f;
                }
            }
        }
        __syncthreads();
    }

    // ---- reduce planes + store ----
    {
        int t = tid >> 1, o0 = (tid & 1) * 16;
#pragma unroll
        for (int oo = 0; oo < 16; oo++) {
            int o = o0 + oo;
            float s = plane[0 * 128 * PLW + t * PLW + o]
                    + plane[1 * 128 * PLW + t * PLW + o]
                    + plane[2 * 128 * PLW + t * PLW + o]
                    + plane[3 * 128 * PLW + t * PLW + o];
            if (STAGE == 1) {
                outp[(size_t)(m0 + t) * 1024 + o * 32 + g] = s;
            } else {
                size_t idx = (size_t)(m0 + t) * 1024 + g * 32 + o;
                outp[idx] = s * ratio[m0 + t] + biasor[idx];
            }
        }
    }
}

// -------------------- mixer: coeffs + ratio per token ----------------------
__global__ void mixer_kernel(const float* __restrict__ c,
                             const float* __restrict__ Wm1, const float* __restrict__ bm1,
                             const float* __restrict__ Wm2, const float* __restrict__ bm2,
                             const float* __restrict__ Wr,  const float* __restrict__ br,
                             float* __restrict__ coeffs, float* __restrict__ ratio)
{
    __shared__ float cs[C_DIM];
    __shared__ float ms[C_DIM];
    __shared__ float red[C_DIM];
    __shared__ float lg[K_EXP];
    int t = blockIdx.x, tid = threadIdx.x;

    cs[tid] = c[t * C_DIM + tid];
    __syncthreads();

    float acc = bm1[tid];
#pragma unroll 8
    for (int i = 0; i < C_DIM; i++) acc += cs[i] * Wm1[i * C_DIM + tid];
    ms[tid] = silu_f(acc);
    red[tid] = cs[tid] * Wr[tid];
    __syncthreads();

    if (tid < K_EXP) {
        float l = bm2[tid];
#pragma unroll 8
        for (int i = 0; i < C_DIM; i++) l += ms[i] * Wm2[i * K_EXP + tid];
        lg[tid] = l;
    }
    for (int s = 128; s > 0; s >>= 1) {
        __syncthreads();
        if (tid < s) red[tid] += red[tid + s];
    }
    __syncthreads();

    if (tid == 0) {
        ratio[t] = red[0] + br[0];
        float mx = fmaxf(fmaxf(lg[0], lg[1]), fmaxf(lg[2], lg[3]));
        float e0 = __expf(lg[0] - mx), e1 = __expf(lg[1] - mx);
        float e2 = __expf(lg[2] - mx), e3 = __expf(lg[3] - mx);
        float inv = 1.0f / (e0 + e1 + e2 + e3);
        coeffs[t * 4 + 0] = e0 * inv;
        coeffs[t * 4 + 1] = e1 * inv;
        coeffs[t * 4 + 2] = e2 * inv;
        coeffs[t * 4 + 3] = e3 * inv;
    }
}

// ---------------------------------------------------------------------------
extern "C" void kernel_launch(void* const* d_in, const int* in_sizes, int n_in,
                              void* d_out, int out_size)
{
    const float* x   = (const float*)d_in[0];
    const float* Wc  = (const float*)d_in[1];
    const float* bc  = (const float*)d_in[2];
    const float* W1a = (const float*)d_in[3];
    const float* b1a = (const float*)d_in[4];
    const float* W1b = (const float*)d_in[5];
    const float* b1b = (const float*)d_in[6];
    const float* W2a = (const float*)d_in[7];
    const float* b2a = (const float*)d_in[8];
    const float* W2b = (const float*)d_in[9];
    const float* b2b = (const float*)d_in[10];
    const float* Wm1 = (const float*)d_in[11];
    const float* bm1 = (const float*)d_in[12];
    const float* Wm2 = (const float*)d_in[13];
    const float* bm2 = (const float*)d_in[14];
    const float* Wb  = (const float*)d_in[15];
    const float* bb  = (const float*)d_in[16];
    const float* Wr  = (const float*)d_in[17];
    const float* br  = (const float*)d_in[18];
    float* out = (float*)d_out;

    float *p_c, *p_co, *p_ra, *p_bi, *p_x1;
    __half *p_a16;
    cudaGetSymbolAddress((void**)&p_c,   g_c);
    cudaGetSymbolAddress((void**)&p_a16, g_A16);
    cudaGetSymbolAddress((void**)&p_co,  g_coeffs);
    cudaGetSymbolAddress((void**)&p_ra,  g_ratio);
    cudaGetSymbolAddress((void**)&p_bi,  g_biasor);
    cudaGetSymbolAddress((void**)&p_x1,  g_x1oT);

    cudaFuncSetAttribute(bgemm_fused<1>,
                         cudaFuncAttributeMaxDynamicSharedMemorySize, FUSED_SMEM);
    cudaFuncSetAttribute(bgemm_fused<2>,
                         cudaFuncAttributeMaxDynamicSharedMemorySize, FUSED_SMEM);

    // 1. c = silu(x @ Wc + bc)
    sgemm64<1><<<dim3(C_DIM / 64, T_TOK / 64, 1), 256>>>(
        x, Wc, p_c, IN_DIM, IN_DIM, C_DIM, C_DIM, bc, nullptr, 0, 0, 0, nullptr);

    // 2. coeffs (softmax), ratio
    mixer_kernel<<<T_TOK, C_DIM>>>(p_c, Wm1, bm1, Wm2, bm2, Wr, br, p_co, p_ra);

    // 3. biasor = c @ Wb + bb
    sgemm64<0><<<dim3(OUT_DIM / 64, T_TOK / 64, 1), 256>>>(
        p_c, Wb, p_bi, C_DIM, C_DIM, OUT_DIM, OUT_DIM, bb, nullptr, 0, 0, 0, nullptr);

    // 4. g1 = coeffs * silu(c @ W1a + b1a)  -> fp16
    sgemm64<2><<<dim3(C_DIM / 64, T_TOK / 64, K_EXP), 256>>>(
        p_c, W1a, nullptr, C_DIM, C_DIM, C_DIM, KC, b1a, p_co,
        C_DIM * C_DIM, C_DIM, C_DIM, p_a16);

    // 5. fused: M1 = g1@W1b + coeffs@b1b; x1oT = monarch-contract(x, M1)
    bgemm_fused<1><<<dim3(T_TOK / 128, 32), 256, FUSED_SMEM>>>(
        p_a16, W1b, x, p_x1, b1b, p_co, p_ra, p_bi);

    // 6. g2 = coeffs * silu(c @ W2a + b2a)  -> fp16
    sgemm64<2><<<dim3(C_DIM / 64, T_TOK / 64, K_EXP), 256>>>(
        p_c, W2a, nullptr, C_DIM, C_DIM, C_DIM, KC, b2a, p_co,
        C_DIM * C_DIM, C_DIM, C_DIM, p_a16);

    // 7. fused: M2 = g2@W2b + coeffs@b2b; out = contract(x1oT)*ratio + biasor
    bgemm_fused<2><<<dim3(T_TOK / 128, 32), 256, FUSED_SMEM>>>(
        p_a16, W2b, p_x1, out, b2b, p_co, p_ra, p_bi);
}

// round 8
// speedup vs baseline: 3.6132x; 1.1955x over previous
#include <cuda_runtime.h>
#include <cuda_bf16.h>
#include <cuda_fp16.h>
#include <cstdint>
#include <cstddef>

// ---------------------------------------------------------------------------
// HyperMoMixLinear on GB300 (sm_103a harness, PLAIN sm_103 ptx target).
// Big hypernet GEMMs (512x32768x1024, x2) on mma.sync fp16, 1-term
// (precision margin measured: 1.46e-5 @ 1-term vs 1e-3 budget).
// M scratch stored fp16 (halves DRAM traffic; bias terms are fp32-exact and
// dominate M's magnitude, diluting the storage rounding).
// Structure = R6's ceiling-hitting GEMM loop (grid 4x256, BK=64, double buf).
// ---------------------------------------------------------------------------

#define T_TOK 512
#define C_DIM 256
#define IN_DIM 1024
#define OUT_DIM 1024
#define K_EXP 4
#define D_BIG 32768
#define KC 1024   // K_EXP * C_DIM  == GEMM K

// -------------------- device scratch (no runtime allocation) ---------------
__device__ float g_c[T_TOK * C_DIM];
__device__ __half g_A16a[T_TOK * KC];
__device__ __half g_A16b[T_TOK * KC];
__device__ float g_coeffs[T_TOK * K_EXP];
__device__ float g_ratio[T_TOK];
__device__ float g_biasor[T_TOK * OUT_DIM];
__device__ float g_x1oT[T_TOK * OUT_DIM];        // stage-1 out, transposed
__device__ __half g_M[(size_t)T_TOK * D_BIG];    // 32 MB scratch (M1 then M2)

__device__ __forceinline__ float silu_f(float v) {
    return v / (1.0f + __expf(-v));
}

__device__ __forceinline__ uint32_t smem_u32(const void* p) {
    uint32_t a;
    asm("{ .reg .u64 t; cvta.to.shared.u64 t, %1; cvt.u32.u64 %0, t; }"
        : "=r"(a) : "l"(p));
    return a;
}

#define CP_ASYNC16(dst, src) \
    asm volatile("cp.async.cg.shared.global [%0], [%1], 16;" \
                 :: "r"(dst), "l"(src) : "memory")
#define CP_COMMIT() asm volatile("cp.async.commit_group;" ::: "memory")
#define CP_WAIT0()  asm volatile("cp.async.wait_group 0;" ::: "memory")

#define LDSM4(r, addr) \
    asm volatile("ldmatrix.sync.aligned.m8n8.x4.shared.b16 {%0,%1,%2,%3}, [%4];" \
        : "=r"((r)[0]), "=r"((r)[1]), "=r"((r)[2]), "=r"((r)[3]) : "r"(addr))
#define LDSM4T(r, addr) \
    asm volatile("ldmatrix.sync.aligned.m8n8.x4.trans.shared.b16 {%0,%1,%2,%3}, [%4];" \
        : "=r"((r)[0]), "=r"((r)[1]), "=r"((r)[2]), "=r"((r)[3]) : "r"(addr))

#define MMA_F16(d, a, b0v, b1v) \
    asm volatile("mma.sync.aligned.m16n8k16.row.col.f32.f16.f16.f32 " \
        "{%0,%1,%2,%3}, {%4,%5,%6,%7}, {%8,%9}, {%0,%1,%2,%3};" \
        : "+f"((d)[0]), "+f"((d)[1]), "+f"((d)[2]), "+f"((d)[3]) \
        : "r"((a)[0]), "r"((a)[1]), "r"((a)[2]), "r"((a)[3]), \
          "r"(b0v), "r"(b1v))

__device__ __forceinline__ uint32_t pack_f16x2(float a, float b) {
    __half2 h = __floats2half2_rn(a, b);
    return *(uint32_t*)&h;
}

// -------------------- small GEMM: 64x64x16 tiles, 4x4 per thread -----------
// EPI 0: out = acc + bias[n]          (fp32)
// EPI 1: out = silu(acc + bias[n])    (fp32)
// EPI 2: coeffs[m,kz]*silu(acc+bias)  -> fp16; z in [0,8): z>>2 picks the
//        (B,bias,out) set so BOTH stages' expert-gens run in ONE launch.
template<int EPI>
__global__ void sgemm64(const float* __restrict__ A, const float* __restrict__ B1,
                        float* __restrict__ Cmat,
                        int Kd, int lda, int ldb, int ldc,
                        const float* __restrict__ bias1,
                        const float* __restrict__ coeffs,
                        int b_zstride, int bias_zstride, int col_zstride,
                        __half* __restrict__ g16a,
                        const float* __restrict__ B2,
                        const float* __restrict__ bias2,
                        __half* __restrict__ g16b)
{
    const int BM = 64, BN = 64, BK = 16;
    __shared__ float As[BK][BM];
    __shared__ float Bs[BK][BN];
    int tid = threadIdx.x;
    int kz = blockIdx.z & 3;
    const float* B = B1;
    const float* bias = bias1;
    __half* g16 = g16a;
    if (EPI == 2 && blockIdx.z >= 4) { B = B2; bias = bias2; g16 = g16b; }
    B += (long)kz * b_zstride;
    bias += kz * bias_zstride;
    int m0 = blockIdx.y * BM;
    int n0 = blockIdx.x * BN;
    int tx = tid % 16, ty = tid / 16;
    int arow = tid / 4, aq = tid % 4;
    int brow = tid / 16, bq = tid % 16;
    float acc[4][4] = {};

    for (int k0 = 0; k0 < Kd; k0 += BK) {
        float4 av = *(const float4*)&A[(m0 + arow) * lda + k0 + aq * 4];
        As[aq * 4 + 0][arow] = av.x;
        As[aq * 4 + 1][arow] = av.y;
        As[aq * 4 + 2][arow] = av.z;
        As[aq * 4 + 3][arow] = av.w;
        *(float4*)&Bs[brow][bq * 4] =
            *(const float4*)&B[(k0 + brow) * ldb + n0 + bq * 4];
        __syncthreads();
#pragma unroll
        for (int k = 0; k < BK; k++) {
            float a[4], b[4];
#pragma unroll
            for (int i = 0; i < 4; i++) a[i] = As[k][ty * 4 + i];
#pragma unroll
            for (int j = 0; j < 4; j++) b[j] = Bs[k][tx * 4 + j];
#pragma unroll
            for (int i = 0; i < 4; i++)
#pragma unroll
                for (int j = 0; j < 4; j++) acc[i][j] += a[i] * b[j];
        }
        __syncthreads();
    }

#pragma unroll
    for (int i = 0; i < 4; i++) {
        int m = m0 + ty * 4 + i;
        float cf = 1.0f;
        if (EPI == 2) cf = coeffs[m * K_EXP + kz];
#pragma unroll
        for (int j = 0; j < 4; j++) {
            int n = n0 + tx * 4 + j;
            float v = acc[i][j] + bias[n];
            if (EPI == 1) v = silu_f(v);
            if (EPI == 2) {
                v = cf * silu_f(v);
                g16[m * ldc + kz * col_zstride + n] = __float2half(v);
            } else {
                Cmat[m * ldc + kz * col_zstride + n] = v;
            }
        }
    }
}

// -------------------- big GEMM on mma.sync (fp16, 1-term) ------------------
// M[512,32768] = A16[512,1024] @ fp16(W[1024,32768]) + coeffs@bB  (fp16 out)
// CTA tile 128x128, BK=64, double-buffered smem, 8 warps of 64x32.
// grid = (4, 256), blockIdx.x = m fastest -> 4 m-CTAs share W slice in L2.
//
// smem per stage (32 KB):
//   A: 128 rows x 128 B fp16 (k=64), swizzled    16 KB
//   B: 64 k-rows x 256 B fp16, swizzled          16 KB
#define STG_SZ 32768
#define B_OFF 16384
#define BGEMM_SMEM (2 * STG_SZ)

__global__ void __launch_bounds__(256, 1) bgemm_half(
    const __half* __restrict__ A16,
    const float* __restrict__ W,
    __half* __restrict__ Mout,
    const float* __restrict__ bB,      // [K_EXP, D_BIG]
    const float* __restrict__ coeffs)  // [T, K_EXP]
{
    extern __shared__ __align__(128) char smem[];
    const uint32_t sbase = smem_u32(smem);
    const int tid = threadIdx.x, wid = tid >> 5, lane = tid & 31;
    const int m0 = blockIdx.x * 128, n0 = blockIdx.y * 128;
    const int warp_m = wid & 1, warp_n = wid >> 1;

    float acc[4][4][4] = {};

    // ---- A cp.async geometry: 4 x 16B per thread per stage (k=64) ----
    const int a_m = tid >> 2;           // + (i&1)*64
    const int a_q = tid & 3;            // + (i>>1)*4
    // ---- B ld/convert/st geometry ----
    const int b_kr = tid >> 5;
    const int b_c4 = tid & 31;
    const uint32_t b_sto = ((uint32_t)(b_c4 * 8)) ^ (((uint32_t)b_kr) << 4);

    // ---- warp ldmatrix geometry (validated in r5-r7) ----
    const int aRow = warp_m * 64 + (lane & 15);
    const uint32_t axor = ((uint32_t)(aRow & 7)) << 4;
    const uint32_t aKhalf = ((lane >> 4) & 1) * 16;
    uint32_t kOffA[2][2];
#pragma unroll
    for (int sel = 0; sel < 2; sel++)
#pragma unroll
        for (int ks = 0; ks < 2; ks++)
            kOffA[sel][ks] = ((uint32_t)(sel * 64 + ks * 32) + aKhalf) ^ axor;
    const uint32_t aBase = (uint32_t)aRow * 128;

    const int kLoc = (lane & 7) | (((lane >> 3) & 1) << 3);
    const uint32_t bxor = ((uint32_t)(kLoc & 7)) << 4;
    const uint32_t bBase = (uint32_t)kLoc * 256;
    uint32_t nbp[2];
#pragma unroll
    for (int p = 0; p < 2; p++)
        nbp[p] = ((uint32_t)((warp_n * 32 + p * 16 + ((lane >> 4) & 1) * 8) * 2)) ^ bxor;

    float bf[16];

    auto issueA = [&](int it, int buf) {
        uint32_t sA = sbase + buf * STG_SZ;
        int k0 = it * 64;
#pragma unroll
        for (int i = 0; i < 4; i++) {
            int m = a_m + (i & 1) * 64;
            int q = a_q + (i >> 1) * 4;
            const __half* src = A16 + (size_t)(m0 + m) * KC + k0 + q * 8;
            uint32_t dst = sA + (uint32_t)m * 128 +
                           (((uint32_t)(q * 16)) ^ (((uint32_t)(m & 7)) << 4));
            CP_ASYNC16(dst, src);
        }
        CP_COMMIT();
    };
    auto loadBh = [&](int it, int h) {
        int k0 = it * 64;
        size_t ncol = (size_t)n0 + b_c4 * 4;
#pragma unroll
        for (int i = 0; i < 4; i++) {
            float4 v = *(const float4*)(W + (size_t)(k0 + h * 32 + b_kr + i * 8) * D_BIG + ncol);
            bf[i * 4 + 0] = v.x; bf[i * 4 + 1] = v.y;
            bf[i * 4 + 2] = v.z; bf[i * 4 + 3] = v.w;
        }
    };
    auto storeBh = [&](int h, int buf) {
#pragma unroll
        for (int i = 0; i < 4; i++) {
            uint2 hv;
            hv.x = pack_f16x2(bf[i * 4 + 0], bf[i * 4 + 1]);
            hv.y = pack_f16x2(bf[i * 4 + 2], bf[i * 4 + 3]);
            uint32_t off = (uint32_t)(h * 32 + b_kr + i * 8) * 256 + b_sto;
            *(uint2*)(smem + buf * STG_SZ + B_OFF + off) = hv;
        }
    };
    auto mmaSel = [&](int sel, int buf) {
        uint32_t sA = sbase + buf * STG_SZ;
        uint32_t sB = sA + B_OFF + sel * 8192;
#pragma unroll
        for (int ks = 0; ks < 2; ks++) {
            uint32_t ah[4][4], bb[2][4];
#pragma unroll
            for (int mt = 0; mt < 4; mt++)
                LDSM4(ah[mt], sA + aBase + mt * 2048 + kOffA[sel][ks]);
#pragma unroll
            for (int p = 0; p < 2; p++)
                LDSM4T(bb[p], sB + ks * 4096 + bBase + nbp[p]);
#pragma unroll
            for (int mt = 0; mt < 4; mt++)
#pragma unroll
                for (int nt = 0; nt < 4; nt++)
                    MMA_F16(acc[mt][nt], ah[mt],
                            bb[nt >> 1][(nt & 1) * 2], bb[nt >> 1][(nt & 1) * 2 + 1]);
        }
    };

    // ---- preamble ----
    issueA(0, 0);
    loadBh(0, 0); storeBh(0, 0);
    loadBh(0, 1); storeBh(1, 0);
    CP_WAIT0();
    __syncthreads();

    // ---- main loop: 16 iterations of BK=64 ----
    for (int it = 0; it < 16; ++it) {
        int cur = it & 1, nxt = cur ^ 1;
        if (it < 15) { issueA(it + 1, nxt); loadBh(it + 1, 0); }
        mmaSel(0, cur);
        if (it < 15) { storeBh(0, nxt); loadBh(it + 1, 1); }
        mmaSel(1, cur);
        if (it < 15) { storeBh(1, nxt); CP_WAIT0(); }
        __syncthreads();
    }

    // ---- epilogue: mixed-expert bias, fp16 stores ----
    const int mw = m0 + warp_m * 64;
    const int nw = n0 + warp_n * 32;
    const int row = lane >> 2, colq = (lane & 3) * 2;
#pragma unroll
    for (int nt = 0; nt < 4; nt++) {
        int n = nw + nt * 8 + colq;
        float bv[K_EXP][2];
#pragma unroll
        for (int e = 0; e < K_EXP; e++) {
            bv[e][0] = bB[(size_t)e * D_BIG + n];
            bv[e][1] = bB[(size_t)e * D_BIG + n + 1];
        }
#pragma unroll
        for (int mt = 0; mt < 4; mt++) {
            int m = mw + mt * 16 + row;
            float4 c0 = *(const float4*)(coeffs + m * 4);
            float4 c1 = *(const float4*)(coeffs + (m + 8) * 4);
            float b00 = c0.x * bv[0][0] + c0.y * bv[1][0] + c0.z * bv[2][0] + c0.w * bv[3][0];
            float b01 = c0.x * bv[0][1] + c0.y * bv[1][1] + c0.z * bv[2][1] + c0.w * bv[3][1];
            float b10 = c1.x * bv[0][0] + c1.y * bv[1][0] + c1.z * bv[2][0] + c1.w * bv[3][0];
            float b11 = c1.x * bv[0][1] + c1.y * bv[1][1] + c1.z * bv[2][1] + c1.w * bv[3][1];
            __half2 h0 = __floats2half2_rn(acc[mt][nt][0] + b00, acc[mt][nt][1] + b01);
            __half2 h1 = __floats2half2_rn(acc[mt][nt][2] + b10, acc[mt][nt][3] + b11);
            *(__half2*)(Mout + (size_t)m * D_BIG + n) = h0;
            *(__half2*)(Mout + (size_t)(m + 8) * D_BIG + n) = h1;
        }
    }
}

// -------------------- mixer: coeffs + ratio per token ----------------------
__global__ void mixer_kernel(const float* __restrict__ c,
                             const float* __restrict__ Wm1, const float* __restrict__ bm1,
                             const float* __restrict__ Wm2, const float* __restrict__ bm2,
                             const float* __restrict__ Wr,  const float* __restrict__ br,
                             float* __restrict__ coeffs, float* __restrict__ ratio)
{
    __shared__ float cs[C_DIM];
    __shared__ float ms[C_DIM];
    __shared__ float red[C_DIM];
    __shared__ float lg[K_EXP];
    int t = blockIdx.x, tid = threadIdx.x;

    cs[tid] = c[t * C_DIM + tid];
    __syncthreads();

    float acc = bm1[tid];
#pragma unroll 8
    for (int i = 0; i < C_DIM; i++) acc += cs[i] * Wm1[i * C_DIM + tid];
    ms[tid] = silu_f(acc);
    red[tid] = cs[tid] * Wr[tid];
    __syncthreads();

    if (tid < K_EXP) {
        float l = bm2[tid];
#pragma unroll 8
        for (int i = 0; i < C_DIM; i++) l += ms[i] * Wm2[i * K_EXP + tid];
        lg[tid] = l;
    }
    for (int s = 128; s > 0; s >>= 1) {
        __syncthreads();
        if (tid < s) red[tid] += red[tid + s];
    }
    __syncthreads();

    if (tid == 0) {
        ratio[t] = red[0] + br[0];
        float mx = fmaxf(fmaxf(lg[0], lg[1]), fmaxf(lg[2], lg[3]));
        float e0 = __expf(lg[0] - mx), e1 = __expf(lg[1] - mx);
        float e2 = __expf(lg[2] - mx), e3 = __expf(lg[3] - mx);
        float inv = 1.0f / (e0 + e1 + e2 + e3);
        coeffs[t * 4 + 0] = e0 * inv;
        coeffs[t * 4 + 1] = e1 * inv;
        coeffs[t * 4 + 2] = e2 * inv;
        coeffs[t * 4 + 3] = e3 * inv;
    }
}

// -------------------- Monarch stage: per-(token,g) 32x32 GEMV (fp16 M) -----
template<int STAGE>
__global__ void monarch_kernel(const float* __restrict__ X,
                               const __half* __restrict__ Mbuf,
                               float* __restrict__ out,
                               const float* __restrict__ ratio,
                               const float* __restrict__ biasor)
{
    __shared__ float xs[1024];
    int t = blockIdx.x;
    int tid = threadIdx.x;   // 256
#pragma unroll
    for (int i = tid; i < 1024; i += 256) xs[i] = X[t * 1024 + i];
    __syncthreads();

    int o = tid & 31, w = tid >> 5;
    const __half* Mrow = Mbuf + (size_t)t * D_BIG;
#pragma unroll
    for (int gi = 0; gi < 4; gi++) {
        int g = w * 4 + gi;
        float acc = 0.0f;
        const __half* mp = Mrow + g * 1024 + o;
#pragma unroll
        for (int i = 0; i < 32; i++) acc += xs[g * 32 + i] * __half2float(mp[i * 32]);
        if (STAGE == 1) {
            out[t * 1024 + o * 32 + g] = acc;           // transposed for stage 2
        } else {
            int idx = t * 1024 + g * 32 + o;
            out[idx] = acc * ratio[t] + biasor[idx];
        }
    }
}

// ---------------------------------------------------------------------------
extern "C" void kernel_launch(void* const* d_in, const int* in_sizes, int n_in,
                              void* d_out, int out_size)
{
    const float* x   = (const float*)d_in[0];
    const float* Wc  = (const float*)d_in[1];
    const float* bc  = (const float*)d_in[2];
    const float* W1a = (const float*)d_in[3];
    const float* b1a = (const float*)d_in[4];
    const float* W1b = (const float*)d_in[5];
    const float* b1b = (const float*)d_in[6];
    const float* W2a = (const float*)d_in[7];
    const float* b2a = (const float*)d_in[8];
    const float* W2b = (const float*)d_in[9];
    const float* b2b = (const float*)d_in[10];
    const float* Wm1 = (const float*)d_in[11];
    const float* bm1 = (const float*)d_in[12];
    const float* Wm2 = (const float*)d_in[13];
    const float* bm2 = (const float*)d_in[14];
    const float* Wb  = (const float*)d_in[15];
    const float* bb  = (const float*)d_in[16];
    const float* Wr  = (const float*)d_in[17];
    const float* br  = (const float*)d_in[18];
    float* out = (float*)d_out;

    float *p_c, *p_co, *p_ra, *p_bi, *p_x1;
    __half *p_a, *p_b, *p_M;
    cudaGetSymbolAddress((void**)&p_c,  g_c);
    cudaGetSymbolAddress((void**)&p_a,  g_A16a);
    cudaGetSymbolAddress((void**)&p_b,  g_A16b);
    cudaGetSymbolAddress((void**)&p_co, g_coeffs);
    cudaGetSymbolAddress((void**)&p_ra, g_ratio);
    cudaGetSymbolAddress((void**)&p_bi, g_biasor);
    cudaGetSymbolAddress((void**)&p_x1, g_x1oT);
    cudaGetSymbolAddress((void**)&p_M,  g_M);

    cudaFuncSetAttribute(bgemm_half, cudaFuncAttributeMaxDynamicSharedMemorySize,
                         BGEMM_SMEM);

    // 1. c = silu(x @ Wc + bc)
    sgemm64<1><<<dim3(C_DIM / 64, T_TOK / 64, 1), 256>>>(
        x, Wc, p_c, IN_DIM, IN_DIM, C_DIM, C_DIM, bc, nullptr, 0, 0, 0,
        nullptr, nullptr, nullptr, nullptr);

    // 2. coeffs (softmax), ratio
    mixer_kernel<<<T_TOK, C_DIM>>>(p_c, Wm1, bm1, Wm2, bm2, Wr, br, p_co, p_ra);

    // 3. biasor = c @ Wb + bb
    sgemm64<0><<<dim3(OUT_DIM / 64, T_TOK / 64, 1), 256>>>(
        p_c, Wb, p_bi, C_DIM, C_DIM, OUT_DIM, OUT_DIM, bb, nullptr, 0, 0, 0,
        nullptr, nullptr, nullptr, nullptr);

    // 4. BOTH expert-gens in one launch (z<4: stage1, z>=4: stage2) -> fp16
    sgemm64<2><<<dim3(C_DIM / 64, T_TOK / 64, 2 * K_EXP), 256>>>(
        p_c, W1a, nullptr, C_DIM, C_DIM, C_DIM, KC, b1a, p_co,
        C_DIM * C_DIM, C_DIM, C_DIM, p_a, W2a, b2a, p_b);

    // 5. M1 = g1 @ W1b + coeffs @ b1b  (fp16 out)
    bgemm_half<<<dim3(T_TOK / 128, D_BIG / 128), 256, BGEMM_SMEM>>>(
        p_a, W1b, p_M, b1b, p_co);

    // 6. Monarch stage 1 (writes transposed)
    monarch_kernel<1><<<T_TOK, 256>>>(x, p_M, p_x1, nullptr, nullptr);

    // 7. M2 = g2 @ W2b + coeffs @ b2b
    bgemm_half<<<dim3(T_TOK / 128, D_BIG / 128), 256, BGEMM_SMEM>>>(
        p_b, W2b, p_M, b2b, p_co);

    // 8. Monarch stage 2 + final epilogue
    monarch_kernel<2><<<T_TOK, 256>>>(p_x1, p_M, out, p_ra, p_bi);
}

// round 9
// speedup vs baseline: 4.0340x; 1.1165x over previous
#include <cuda_runtime.h>
#include <cuda_bf16.h>
#include <cuda_fp16.h>
#include <cstdint>
#include <cstddef>

// ---------------------------------------------------------------------------
// HyperMoMixLinear on GB300 (sm_103a harness, PLAIN sm_103 ptx target).
// Big hypernet GEMMs (512x32768x1024, x2) on mma.sync fp16, 1-term.
// R9: W pre-converted to fp16 (removes fp32-load+convert from the hot loop),
// both operands cp.async'd, 4-stage pipeline, both GEMMs in one launch.
// ---------------------------------------------------------------------------

#define T_TOK 512
#define C_DIM 256
#define IN_DIM 1024
#define OUT_DIM 1024
#define K_EXP 4
#define D_BIG 32768
#define KC 1024   // K_EXP * C_DIM  == GEMM K
#define W_ELEMS ((size_t)KC * D_BIG)

// -------------------- device scratch (no runtime allocation) ---------------
__device__ float g_c[T_TOK * C_DIM];
__device__ __half g_A16a[T_TOK * KC];
__device__ __half g_A16b[T_TOK * KC];
__device__ float g_coeffs[T_TOK * K_EXP];
__device__ float g_ratio[T_TOK];
__device__ float g_biasor[T_TOK * OUT_DIM];
__device__ float g_x1oT[T_TOK * OUT_DIM];          // stage-1 out, transposed
__device__ __half g_M[2 * (size_t)T_TOK * D_BIG];  // 2 x 32 MB (M1, M2)
__device__ __half g_W16[2 * W_ELEMS];              // 128 MB fp16 weights

__device__ __forceinline__ float silu_f(float v) {
    return v / (1.0f + __expf(-v));
}

__device__ __forceinline__ uint32_t smem_u32(const void* p) {
    uint32_t a;
    asm("{ .reg .u64 t; cvta.to.shared.u64 t, %1; cvt.u32.u64 %0, t; }"
        : "=r"(a) : "l"(p));
    return a;
}

#define CP_ASYNC16(dst, src) \
    asm volatile("cp.async.cg.shared.global [%0], [%1], 16;" \
                 :: "r"(dst), "l"(src) : "memory")
#define CP_COMMIT() asm volatile("cp.async.commit_group;" ::: "memory")
#define CP_WAIT0()  asm volatile("cp.async.wait_group 0;" ::: "memory")
#define CP_WAIT2()  asm volatile("cp.async.wait_group 2;" ::: "memory")

#define LDSM4(r, addr) \
    asm volatile("ldmatrix.sync.aligned.m8n8.x4.shared.b16 {%0,%1,%2,%3}, [%4];" \
        : "=r"((r)[0]), "=r"((r)[1]), "=r"((r)[2]), "=r"((r)[3]) : "r"(addr))
#define LDSM4T(r, addr) \
    asm volatile("ldmatrix.sync.aligned.m8n8.x4.trans.shared.b16 {%0,%1,%2,%3}, [%4];" \
        : "=r"((r)[0]), "=r"((r)[1]), "=r"((r)[2]), "=r"((r)[3]) : "r"(addr))

#define MMA_F16(d, a, b0v, b1v) \
    asm volatile("mma.sync.aligned.m16n8k16.row.col.f32.f16.f16.f32 " \
        "{%0,%1,%2,%3}, {%4,%5,%6,%7}, {%8,%9}, {%0,%1,%2,%3};" \
        : "+f"((d)[0]), "+f"((d)[1]), "+f"((d)[2]), "+f"((d)[3]) \
        : "r"((a)[0]), "r"((a)[1]), "r"((a)[2]), "r"((a)[3]), \
          "r"(b0v), "r"(b1v))

// -------------------- W fp32 -> fp16 (both weights, one launch) ------------
// grid (16384, 2), 256 thr; 8 elems/thread.
__global__ void convert_w(const float* __restrict__ W1,
                          const float* __restrict__ W2,
                          __half* __restrict__ O)
{
    const float* W = blockIdx.y ? W2 : W1;
    __half* dst = O + (size_t)blockIdx.y * W_ELEMS;
    size_t base = ((size_t)blockIdx.x * 256 + threadIdx.x) * 8;
    float4 v0 = *(const float4*)(W + base);
    float4 v1 = *(const float4*)(W + base + 4);
    __half2 h0 = __floats2half2_rn(v0.x, v0.y);
    __half2 h1 = __floats2half2_rn(v0.z, v0.w);
    __half2 h2 = __floats2half2_rn(v1.x, v1.y);
    __half2 h3 = __floats2half2_rn(v1.z, v1.w);
    uint4 o;
    o.x = *(uint32_t*)&h0; o.y = *(uint32_t*)&h1;
    o.z = *(uint32_t*)&h2; o.w = *(uint32_t*)&h3;
    *(uint4*)(dst + base) = o;
}

// -------------------- small GEMM: 64x64x16 tiles, 4x4 per thread -----------
// EPI 0: out = acc + bias[n]          (fp32)
// EPI 1: out = silu(acc + bias[n])    (fp32)
// EPI 2: coeffs[m,kz]*silu(acc+bias)  -> fp16; z in [0,8): z>>2 picks stage
template<int EPI>
__global__ void sgemm64(const float* __restrict__ A, const float* __restrict__ B1,
                        float* __restrict__ Cmat,
                        int Kd, int lda, int ldb, int ldc,
                        const float* __restrict__ bias1,
                        const float* __restrict__ coeffs,
                        int b_zstride, int bias_zstride, int col_zstride,
                        __half* __restrict__ g16a,
                        const float* __restrict__ B2,
                        const float* __restrict__ bias2,
                        __half* __restrict__ g16b)
{
    const int BM = 64, BN = 64, BK = 16;
    __shared__ float As[BK][BM];
    __shared__ float Bs[BK][BN];
    int tid = threadIdx.x;
    int kz = blockIdx.z & 3;
    const float* B = B1;
    const float* bias = bias1;
    __half* g16 = g16a;
    if (EPI == 2 && blockIdx.z >= 4) { B = B2; bias = bias2; g16 = g16b; }
    B += (long)kz * b_zstride;
    bias += kz * bias_zstride;
    int m0 = blockIdx.y * BM;
    int n0 = blockIdx.x * BN;
    int tx = tid % 16, ty = tid / 16;
    int arow = tid / 4, aq = tid % 4;
    int brow = tid / 16, bq = tid % 16;
    float acc[4][4] = {};

    for (int k0 = 0; k0 < Kd; k0 += BK) {
        float4 av = *(const float4*)&A[(m0 + arow) * lda + k0 + aq * 4];
        As[aq * 4 + 0][arow] = av.x;
        As[aq * 4 + 1][arow] = av.y;
        As[aq * 4 + 2][arow] = av.z;
        As[aq * 4 + 3][arow] = av.w;
        *(float4*)&Bs[brow][bq * 4] =
            *(const float4*)&B[(k0 + brow) * ldb + n0 + bq * 4];
        __syncthreads();
#pragma unroll
        for (int k = 0; k < BK; k++) {
            float a[4], b[4];
#pragma unroll
            for (int i = 0; i < 4; i++) a[i] = As[k][ty * 4 + i];
#pragma unroll
            for (int j = 0; j < 4; j++) b[j] = Bs[k][tx * 4 + j];
#pragma unroll
            for (int i = 0; i < 4; i++)
#pragma unroll
                for (int j = 0; j < 4; j++) acc[i][j] += a[i] * b[j];
        }
        __syncthreads();
    }

#pragma unroll
    for (int i = 0; i < 4; i++) {
        int m = m0 + ty * 4 + i;
        float cf = 1.0f;
        if (EPI == 2) cf = coeffs[m * K_EXP + kz];
#pragma unroll
        for (int j = 0; j < 4; j++) {
            int n = n0 + tx * 4 + j;
            float v = acc[i][j] + bias[n];
            if (EPI == 1) v = silu_f(v);
            if (EPI == 2) {
                v = cf * silu_f(v);
                g16[m * ldc + kz * col_zstride + n] = __float2half(v);
            } else {
                Cmat[m * ldc + kz * col_zstride + n] = v;
            }
        }
    }
}

// -------------------- big GEMM on mma.sync (fp16, both operands cp.async) --
// z = blockIdx.z picks (A16, W16 plane, bB, Mout plane).
// CTA tile 128x128, BK=64, 4-stage cp.async pipeline, 8 warps of 64x32.
// smem per stage (32 KB): A 128x128B fp16 | B 64x256B fp16, both swizzled.
#define STG_SZ 32768
#define B_OFF 16384
#define NSTG 4
#define BGEMM_SMEM (NSTG * STG_SZ)   // 128 KB

__global__ void __launch_bounds__(256, 1) bgemm_half(
    const __half* __restrict__ A16a, const __half* __restrict__ A16b,
    const __half* __restrict__ W16,
    __half* __restrict__ Mbuf,
    const float* __restrict__ bB1, const float* __restrict__ bB2,
    const float* __restrict__ coeffs)
{
    extern __shared__ __align__(128) char smem[];
    const uint32_t sbase = smem_u32(smem);
    const int tid = threadIdx.x, wid = tid >> 5, lane = tid & 31;
    const int m0 = blockIdx.x * 128, n0 = blockIdx.y * 128;
    const int z = blockIdx.z;
    const int warp_m = wid & 1, warp_n = wid >> 1;

    const __half* A16 = z ? A16b : A16a;
    const __half* W = W16 + (size_t)z * W_ELEMS;
    const float* bB = z ? bB2 : bB1;
    __half* Mout = Mbuf + (size_t)z * T_TOK * D_BIG;

    float acc[4][4][4] = {};

    // ---- cp.async geometry ----
    const int a_m = tid >> 2;            // + (i&1)*64
    const int a_q = tid & 3;             // + (i>>1)*4
    const int b_k = tid >> 2;            // 0..63
    const int b_cq = tid & 3;            // + i*4 -> 16 chunks of 16B

    // ---- warp ldmatrix geometry ----
    const int aRow = warp_m * 64 + (lane & 15);
    const uint32_t axor = ((uint32_t)(aRow & 7)) << 4;
    const uint32_t aKhalf = ((lane >> 4) & 1) * 16;
    uint32_t kOff[4];
#pragma unroll
    for (int ks = 0; ks < 4; ks++)
        kOff[ks] = ((uint32_t)(ks * 32) + aKhalf) ^ axor;
    const uint32_t aBase = (uint32_t)aRow * 128;

    const int kLoc = (lane & 7) | (((lane >> 3) & 1) << 3);
    const uint32_t bxor = ((uint32_t)(kLoc & 7)) << 4;
    const uint32_t bBase = (uint32_t)kLoc * 256;
    uint32_t nbp[2];
#pragma unroll
    for (int p = 0; p < 2; p++)
        nbp[p] = ((uint32_t)((warp_n * 32 + p * 16 + ((lane >> 4) & 1) * 8) * 2)) ^ bxor;

    auto issue = [&](int it, int buf) {
        uint32_t s = sbase + buf * STG_SZ;
        int k0 = it * 64;
#pragma unroll
        for (int i = 0; i < 4; i++) {
            int m = a_m + (i & 1) * 64;
            int q = a_q + (i >> 1) * 4;
            const __half* src = A16 + (size_t)(m0 + m) * KC + k0 + q * 8;
            uint32_t dst = s + (uint32_t)m * 128 +
                           (((uint32_t)(q * 16)) ^ (((uint32_t)(m & 7)) << 4));
            CP_ASYNC16(dst, src);
        }
#pragma unroll
        for (int i = 0; i < 4; i++) {
            int chunk = b_cq + i * 4;
            const __half* src = W + (size_t)(k0 + b_k) * D_BIG + n0 + chunk * 8;
            uint32_t dst = s + B_OFF + (uint32_t)b_k * 256 +
                           (((uint32_t)(chunk * 16)) ^ (((uint32_t)(b_k & 7)) << 4));
            CP_ASYNC16(dst, src);
        }
        CP_COMMIT();
    };
    auto mmaStage = [&](int buf) {
        uint32_t sA = sbase + buf * STG_SZ;
        uint32_t sB = sA + B_OFF;
#pragma unroll
        for (int ks = 0; ks < 4; ks++) {
            uint32_t ah[4][4], bb[2][4];
#pragma unroll
            for (int mt = 0; mt < 4; mt++)
                LDSM4(ah[mt], sA + aBase + mt * 2048 + kOff[ks]);
#pragma unroll
            for (int p = 0; p < 2; p++)
                LDSM4T(bb[p], sB + ks * 4096 + bBase + nbp[p]);
#pragma unroll
            for (int mt = 0; mt < 4; mt++)
#pragma unroll
                for (int nt = 0; nt < 4; nt++)
                    MMA_F16(acc[mt][nt], ah[mt],
                            bb[nt >> 1][(nt & 1) * 2], bb[nt >> 1][(nt & 1) * 2 + 1]);
        }
    };

    // ---- prologue: 3 stages in flight ----
    issue(0, 0); issue(1, 1); issue(2, 2);

    // ---- main loop: 16 iterations of BK=64 ----
    for (int it = 0; it < 16; ++it) {
        CP_WAIT2();
        __syncthreads();
        if (it + 3 < 16) issue(it + 3, (it + 3) & (NSTG - 1));
        else CP_COMMIT();                 // keep group count in lockstep
        mmaStage(it & (NSTG - 1));
    }

    // ---- epilogue: mixed-expert bias, fp16 stores ----
    const int mw = m0 + warp_m * 64;
    const int nw = n0 + warp_n * 32;
    const int row = lane >> 2, colq = (lane & 3) * 2;
#pragma unroll
    for (int nt = 0; nt < 4; nt++) {
        int n = nw + nt * 8 + colq;
        float bv[K_EXP][2];
#pragma unroll
        for (int e = 0; e < K_EXP; e++) {
            bv[e][0] = bB[(size_t)e * D_BIG + n];
            bv[e][1] = bB[(size_t)e * D_BIG + n + 1];
        }
#pragma unroll
        for (int mt = 0; mt < 4; mt++) {
            int m = mw + mt * 16 + row;
            float4 c0 = *(const float4*)(coeffs + m * 4);
            float4 c1 = *(const float4*)(coeffs + (m + 8) * 4);
            float b00 = c0.x * bv[0][0] + c0.y * bv[1][0] + c0.z * bv[2][0] + c0.w * bv[3][0];
            float b01 = c0.x * bv[0][1] + c0.y * bv[1][1] + c0.z * bv[2][1] + c0.w * bv[3][1];
            float b10 = c1.x * bv[0][0] + c1.y * bv[1][0] + c1.z * bv[2][0] + c1.w * bv[3][0];
            float b11 = c1.x * bv[0][1] + c1.y * bv[1][1] + c1.z * bv[2][1] + c1.w * bv[3][1];
            __half2 h0 = __floats2half2_rn(acc[mt][nt][0] + b00, acc[mt][nt][1] + b01);
            __half2 h1 = __floats2half2_rn(acc[mt][nt][2] + b10, acc[mt][nt][3] + b11);
            *(__half2*)(Mout + (size_t)m * D_BIG + n) = h0;
            *(__half2*)(Mout + (size_t)(m + 8) * D_BIG + n) = h1;
        }
    }
}

// -------------------- mixer: coeffs + ratio per token ----------------------
__global__ void mixer_kernel(const float* __restrict__ c,
                             const float* __restrict__ Wm1, const float* __restrict__ bm1,
                             const float* __restrict__ Wm2, const float* __restrict__ bm2,
                             const float* __restrict__ Wr,  const float* __restrict__ br,
                             float* __restrict__ coeffs, float* __restrict__ ratio)
{
    __shared__ float cs[C_DIM];
    __shared__ float ms[C_DIM];
    __shared__ float red[C_DIM];
    __shared__ float lg[K_EXP];
    int t = blockIdx.x, tid = threadIdx.x;

    cs[tid] = c[t * C_DIM + tid];
    __syncthreads();

    float acc = bm1[tid];
#pragma unroll 8
    for (int i = 0; i < C_DIM; i++) acc += cs[i] * Wm1[i * C_DIM + tid];
    ms[tid] = silu_f(acc);
    red[tid] = cs[tid] * Wr[tid];
    __syncthreads();

    if (tid < K_EXP) {
        float l = bm2[tid];
#pragma unroll 8
        for (int i = 0; i < C_DIM; i++) l += ms[i] * Wm2[i * K_EXP + tid];
        lg[tid] = l;
    }
    for (int s = 128; s > 0; s >>= 1) {
        __syncthreads();
        if (tid < s) red[tid] += red[tid + s];
    }
    __syncthreads();

    if (tid == 0) {
        ratio[t] = red[0] + br[0];
        float mx = fmaxf(fmaxf(lg[0], lg[1]), fmaxf(lg[2], lg[3]));
        float e0 = __expf(lg[0] - mx), e1 = __expf(lg[1] - mx);
        float e2 = __expf(lg[2] - mx), e3 = __expf(lg[3] - mx);
        float inv = 1.0f / (e0 + e1 + e2 + e3);
        coeffs[t * 4 + 0] = e0 * inv;
        coeffs[t * 4 + 1] = e1 * inv;
        coeffs[t * 4 + 2] = e2 * inv;
        coeffs[t * 4 + 3] = e3 * inv;
    }
}

// -------------------- Monarch stage: per-(token,g) 32x32 GEMV (fp16 M) -----
template<int STAGE>
__global__ void monarch_kernel(const float* __restrict__ X,
                               const __half* __restrict__ Mbuf,
                               float* __restrict__ out,
                               const float* __restrict__ ratio,
                               const float* __restrict__ biasor)
{
    __shared__ float xs[1024];
    int t = blockIdx.x;
    int tid = threadIdx.x;   // 256
#pragma unroll
    for (int i = tid; i < 1024; i += 256) xs[i] = X[t * 1024 + i];
    __syncthreads();

    int o = tid & 31, w = tid >> 5;
    const __half* Mrow = Mbuf + (size_t)t * D_BIG;
#pragma unroll
    for (int gi = 0; gi < 4; gi++) {
        int g = w * 4 + gi;
        float acc = 0.0f;
        const __half* mp = Mrow + g * 1024 + o;
#pragma unroll
        for (int i = 0; i < 32; i++) acc += xs[g * 32 + i] * __half2float(mp[i * 32]);
        if (STAGE == 1) {
            out[t * 1024 + o * 32 + g] = acc;           // transposed for stage 2
        } else {
            int idx = t * 1024 + g * 32 + o;
            out[idx] = acc * ratio[t] + biasor[idx];
        }
    }
}

// ---------------------------------------------------------------------------
extern "C" void kernel_launch(void* const* d_in, const int* in_sizes, int n_in,
                              void* d_out, int out_size)
{
    const float* x   = (const float*)d_in[0];
    const float* Wc  = (const float*)d_in[1];
    const float* bc  = (const float*)d_in[2];
    const float* W1a = (const float*)d_in[3];
    const float* b1a = (const float*)d_in[4];
    const float* W1b = (const float*)d_in[5];
    const float* b1b = (const float*)d_in[6];
    const float* W2a = (const float*)d_in[7];
    const float* b2a = (const float*)d_in[8];
    const float* W2b = (const float*)d_in[9];
    const float* b2b = (const float*)d_in[10];
    const float* Wm1 = (const float*)d_in[11];
    const float* bm1 = (const float*)d_in[12];
    const float* Wm2 = (const float*)d_in[13];
    const float* bm2 = (const float*)d_in[14];
    const float* Wb  = (const float*)d_in[15];
    const float* bb  = (const float*)d_in[16];
    const float* Wr  = (const float*)d_in[17];
    const float* br  = (const float*)d_in[18];
    float* out = (float*)d_out;

    float *p_c, *p_co, *p_ra, *p_bi, *p_x1;
    __half *p_a, *p_b, *p_M, *p_w16;
    cudaGetSymbolAddress((void**)&p_c,   g_c);
    cudaGetSymbolAddress((void**)&p_a,   g_A16a);
    cudaGetSymbolAddress((void**)&p_b,   g_A16b);
    cudaGetSymbolAddress((void**)&p_co,  g_coeffs);
    cudaGetSymbolAddress((void**)&p_ra,  g_ratio);
    cudaGetSymbolAddress((void**)&p_bi,  g_biasor);
    cudaGetSymbolAddress((void**)&p_x1,  g_x1oT);
    cudaGetSymbolAddress((void**)&p_M,   g_M);
    cudaGetSymbolAddress((void**)&p_w16, g_W16);

    cudaFuncSetAttribute(bgemm_half, cudaFuncAttributeMaxDynamicSharedMemorySize,
                         BGEMM_SMEM);

    // 0. W1b/W2b fp32 -> fp16 (one launch)
    convert_w<<<dim3(16384, 2), 256>>>(W1b, W2b, p_w16);

    // 1. c = silu(x @ Wc + bc)
    sgemm64<1><<<dim3(C_DIM / 64, T_TOK / 64, 1), 256>>>(
        x, Wc, p_c, IN_DIM, IN_DIM, C_DIM, C_DIM, bc, nullptr, 0, 0, 0,
        nullptr, nullptr, nullptr, nullptr);

    // 2. coeffs (softmax), ratio
    mixer_kernel<<<T_TOK, C_DIM>>>(p_c, Wm1, bm1, Wm2, bm2, Wr, br, p_co, p_ra);

    // 3. biasor = c @ Wb + bb
    sgemm64<0><<<dim3(OUT_DIM / 64, T_TOK / 64, 1), 256>>>(
        p_c, Wb, p_bi, C_DIM, C_DIM, OUT_DIM, OUT_DIM, bb, nullptr, 0, 0, 0,
        nullptr, nullptr, nullptr, nullptr);

    // 4. BOTH expert-gens in one launch (z<4: stage1, z>=4: stage2) -> fp16
    sgemm64<2><<<dim3(C_DIM / 64, T_TOK / 64, 2 * K_EXP), 256>>>(
        p_c, W1a, nullptr, C_DIM, C_DIM, C_DIM, KC, b1a, p_co,
        C_DIM * C_DIM, C_DIM, C_DIM, p_a, W2a, b2a, p_b);

    // 5. BOTH big GEMMs in one launch (z picks stage)
    bgemm_half<<<dim3(T_TOK / 128, D_BIG / 128, 2), 256, BGEMM_SMEM>>>(
        p_a, p_b, p_w16, p_M, b1b, b2b, p_co);

    // 6. Monarch stage 1 (writes transposed)
    monarch_kernel<1><<<T_TOK, 256>>>(x, p_M, p_x1, nullptr, nullptr);

    // 7. Monarch stage 2 + final epilogue
    monarch_kernel<2><<<T_TOK, 256>>>(
        p_x1, p_M + (size_t)T_TOK * D_BIG, out, p_ra, p_bi);
}